// round 7
// baseline (speedup 1.0000x reference)
#include <cuda_runtime.h>
#include <cuda_bf16.h>
#include <math.h>
#include <stdint.h>

// ---------------------------------------------------------------------------
// Model constants
// ---------------------------------------------------------------------------
#define Lc 2
#define Hc 2048
#define NHc 32
#define NKVc 4
#define HDc 64
#define Ic 5632
#define Bc 2
#define Sc 1024
#define Tc (Bc * Sc)                   // 2048 tokens
#define QKVN ((NHc + 2 * NKVc) * HDc)  // 2560
#define GUN (2 * Ic)                   // 11264
#define EPSc 1e-5f

// ---------------------------------------------------------------------------
// Scratch (static device globals; no allocation allowed)
// ---------------------------------------------------------------------------
__device__ float g_res [Tc * Hc];
__device__ float g_qkv [Tc * QKVN];
__device__ float g_kc  [Bc * NKVc * Sc * HDc];
__device__ float g_vc  [Bc * NKVc * Sc * HDc];
__device__ float g_gu  [(size_t)Tc * GUN];
__device__ float g_h   [Tc * Hc];

// split activations (GEMM A operands)
__device__ __nv_bfloat16 g_hn_hi [Tc * Hc];
__device__ __nv_bfloat16 g_hn_lo [Tc * Hc];
__device__ __nv_bfloat16 g_at_hi [Tc * Hc];
__device__ __nv_bfloat16 g_at_lo [Tc * Hc];
__device__ __nv_bfloat16 g_ac_hi [(size_t)Tc * Ic];
__device__ __nv_bfloat16 g_ac_lo [(size_t)Tc * Ic];

// Transposed split weights: per layer [qkv_t(QKVN,H) | o_t(H,H) | gu_t(GUN,H) | down_t(H,I)]
#define WT_QKV_OFF 0
#define WT_O_OFF   ((size_t)QKVN * Hc)
#define WT_GU_OFF  (WT_O_OFF + (size_t)Hc * Hc)
#define WT_DN_OFF  (WT_GU_OFF + (size_t)GUN * Hc)
#define WT_PER_L   (WT_DN_OFF + (size_t)Hc * Ic)
__device__ __nv_bfloat16 g_wt_hi[2 * WT_PER_L];
__device__ __nv_bfloat16 g_wt_lo[2 * WT_PER_L];

// ---------------------------------------------------------------------------
// Helpers
// ---------------------------------------------------------------------------
__device__ __forceinline__ void split2(float x, __nv_bfloat16& hi, __nv_bfloat16& lo) {
    hi = __float2bfloat16(x);
    lo = __float2bfloat16(x - __bfloat162float(hi));
}

__device__ __forceinline__ uint32_t smem_u32(const void* p) {
    uint32_t a;
    asm("{ .reg .u64 t; cvta.to.shared.u64 t, %1; cvt.u32.u64 %0, t; }"
        : "=r"(a) : "l"(p));
    return a;
}

__device__ __forceinline__ void cp_async16(uint32_t smem_addr, const void* gptr) {
    asm volatile("cp.async.cg.shared.global [%0], [%1], 16;"
                 :: "r"(smem_addr), "l"(gptr) : "memory");
}
#define CP_COMMIT() asm volatile("cp.async.commit_group;" ::: "memory")
#define CP_WAIT1()  asm volatile("cp.async.wait_group 1;" ::: "memory")

__device__ __forceinline__ void mma_bf16(float* d, const uint32_t* a, const uint32_t* b) {
    asm volatile(
        "mma.sync.aligned.m16n8k16.row.col.f32.bf16.bf16.f32 "
        "{%0,%1,%2,%3}, {%4,%5,%6,%7}, {%8,%9}, {%0,%1,%2,%3};"
        : "+f"(d[0]), "+f"(d[1]), "+f"(d[2]), "+f"(d[3])
        : "r"(a[0]), "r"(a[1]), "r"(a[2]), "r"(a[3]),
          "r"(b[0]), "r"(b[1]));
}

#define LDSM4(R, A) \
    asm volatile("ldmatrix.sync.aligned.m8n8.x4.shared.b16 {%0,%1,%2,%3}, [%4];" \
        : "=r"((R)[0]), "=r"((R)[1]), "=r"((R)[2]), "=r"((R)[3]) : "r"(A))

// ---------------------------------------------------------------------------
// Fused weight prep: transpose + bf16x2 split for all 8 weight matrices.
// ---------------------------------------------------------------------------
#define TILES_PER_LAYER 43008
__global__ void prep_weights(const float* __restrict__ wqkv,
                             const float* __restrict__ wo,
                             const float* __restrict__ wgu,
                             const float* __restrict__ wdn,
                             __nv_bfloat16* __restrict__ wth,
                             __nv_bfloat16* __restrict__ wtl) {
    __shared__ float tile[32][33];
    int bid = blockIdx.x;
    int l = 0;
    if (bid >= TILES_PER_LAYER) { l = 1; bid -= TILES_PER_LAYER; }
    size_t loff = (size_t)l * WT_PER_L;

    const float* src;
    __nv_bfloat16 *hi, *lo;
    int K, N;
    if (bid < 5120) {
        src = wqkv + (size_t)l * Hc * QKVN;
        hi = wth + loff + WT_QKV_OFF; lo = wtl + loff + WT_QKV_OFF;
        K = Hc; N = QKVN;
    } else if (bid < 9216) {
        bid -= 5120;
        src = wo + (size_t)l * Hc * Hc;
        hi = wth + loff + WT_O_OFF; lo = wtl + loff + WT_O_OFF;
        K = Hc; N = Hc;
    } else if (bid < 31744) {
        bid -= 9216;
        src = wgu + (size_t)l * Hc * GUN;
        hi = wth + loff + WT_GU_OFF; lo = wtl + loff + WT_GU_OFF;
        K = Hc; N = GUN;
    } else {
        bid -= 31744;
        src = wdn + (size_t)l * Ic * Hc;
        hi = wth + loff + WT_DN_OFF; lo = wtl + loff + WT_DN_OFF;
        K = Ic; N = Hc;
    }
    int tilesX = N / 32;
    int nb = (bid % tilesX) * 32;
    int kb = (bid / tilesX) * 32;

#pragma unroll
    for (int i = threadIdx.y; i < 32; i += 8)
        tile[i][threadIdx.x] = src[(size_t)(kb + i) * N + nb + threadIdx.x];
    __syncthreads();
#pragma unroll
    for (int i = threadIdx.y; i < 32; i += 8) {
        float v = tile[threadIdx.x][i];
        __nv_bfloat16 h, lv;
        split2(v, h, lv);
        size_t idx = (size_t)(nb + i) * K + kb + threadIdx.x;
        hi[idx] = h;
        lo[idx] = lv;
    }
}

// ---------------------------------------------------------------------------
// bf16x2 split GEMM: C[M,N] = A[M,K] @ Bt[N,K]^T (+ addend)
// 3 terms hi*hi + hi*lo + lo*hi, fp32 accum, term-major ordering.
// Block 128x128, 256 threads (8 warps, 32x64 warp tiles).
// 4-stage (BK=16) ring, processed as PAIRS: one wait_group + barrier per 32-K.
// ---------------------------------------------------------------------------
#define RPITCH 48                   // bytes per smem row (16 bf16 = 32B + 16B pad)
#define ARRB   (128 * RPITCH)       // 6144 per operand array
#define STAGEB (4 * ARRB)           // 24576 per stage
#define GEMM_SMEM (4 * STAGEB)      // 98304 (4 stages)

__global__ void __launch_bounds__(256, 2)
gemm_bf16x2(const __nv_bfloat16* __restrict__ Ahi,
            const __nv_bfloat16* __restrict__ Alo,
            const __nv_bfloat16* __restrict__ Bhi,
            const __nv_bfloat16* __restrict__ Blo,
            float* __restrict__ C, const float* __restrict__ addend,
            int M, int N, int K) {
    extern __shared__ char smraw[];
    uint32_t sbase = smem_u32(smraw);

    const int tid  = threadIdx.x;
    const int warp = tid >> 5;
    const int lane = tid & 31;
    const int wm   = (warp >> 1) * 32;   // warp M offset
    const int wn   = (warp & 1) * 64;    // warp N offset
    const int grp  = lane >> 2;
    const int tig  = lane & 3;

    const int m0 = blockIdx.x * 128;
    const int n0 = blockIdx.y * 128;

    // ldmatrix lane offsets
    const int li = lane >> 3;            // matrix group 0..3
    const int lr = lane & 7;             // row within matrix
    const uint32_t aoffl = (uint32_t)(((li & 1) * 8 + lr) * RPITCH + (li >> 1) * 16);
    const uint32_t boffl = (uint32_t)(((li >> 1) * 8 + lr) * RPITCH + (li & 1) * 16);

    // cp.async staging: thread covers row r0, 16B half of each array
    const int r0   = tid >> 1;           // 0..127
    const int half = tid & 1;
    const uint32_t sdst = (uint32_t)(r0 * RPITCH + half * 16);
    const __nv_bfloat16* pAhi = Ahi + (size_t)(m0 + r0) * K + half * 8;
    const __nv_bfloat16* pAlo = Alo + (size_t)(m0 + r0) * K + half * 8;
    const __nv_bfloat16* pBhi = Bhi + (size_t)(n0 + r0) * K + half * 8;
    const __nv_bfloat16* pBlo = Blo + (size_t)(n0 + r0) * K + half * 8;

    const int nkt = K >> 4;              // 16-wide K tiles (always even here)
    const int npair = nkt >> 1;

    float c[2][8][4];
#pragma unroll
    for (int mt = 0; mt < 2; mt++)
#pragma unroll
        for (int nt = 0; nt < 8; nt++)
#pragma unroll
            for (int i = 0; i < 4; i++) c[mt][nt][i] = 0.f;

    // prologue: stage tiles 0..3; ONE commit group per pair of tiles
#pragma unroll
    for (int pp = 0; pp < 2; pp++) {
#pragma unroll
        for (int t2 = 0; t2 < 2; t2++) {
            int s = pp * 2 + t2;
            uint32_t b = sbase + (uint32_t)s * STAGEB + sdst;
            int ko = s * 16;
            cp_async16(b,            pAhi + ko);
            cp_async16(b + ARRB,     pAlo + ko);
            cp_async16(b + 2 * ARRB, pBhi + ko);
            cp_async16(b + 3 * ARRB, pBlo + ko);
        }
        CP_COMMIT();
    }

    for (int p = 0; p < npair; p++) {
        CP_WAIT1();            // pair p's group complete (own thread)
        __syncthreads();       // all threads' pair-p data visible

        // ---- compute the two K-tiles of pair p (96 MMAs/warp, no barrier) ----
#pragma unroll
        for (int hk = 0; hk < 2; hk++) {
            uint32_t sb = sbase + (uint32_t)((2 * p + hk) & 3) * STAGEB;

            uint32_t ahi[2][4], alo[2][4];
#pragma unroll
            for (int mt = 0; mt < 2; mt++) {
                uint32_t aaddr = sb + (uint32_t)((wm + mt * 16) * RPITCH) + aoffl;
                LDSM4(ahi[mt], aaddr);
                LDSM4(alo[mt], aaddr + ARRB);
            }
#pragma unroll
            for (int nh = 0; nh < 2; nh++) {
                uint32_t bhi[2][4], blo[2][4];
#pragma unroll
                for (int pq = 0; pq < 2; pq++) {
                    uint32_t baddr = sb + 2 * ARRB +
                                     (uint32_t)((wn + nh * 32 + pq * 16) * RPITCH) + boffl;
                    LDSM4(bhi[pq], baddr);
                    LDSM4(blo[pq], baddr + ARRB);
                }
#pragma unroll
                for (int mt = 0; mt < 2; mt++)
#pragma unroll
                    for (int pq = 0; pq < 2; pq++)
#pragma unroll
                        for (int h = 0; h < 2; h++)
                            mma_bf16(c[mt][nh * 4 + pq * 2 + h], ahi[mt], &bhi[pq][h * 2]);
#pragma unroll
                for (int mt = 0; mt < 2; mt++)
#pragma unroll
                    for (int pq = 0; pq < 2; pq++)
#pragma unroll
                        for (int h = 0; h < 2; h++)
                            mma_bf16(c[mt][nh * 4 + pq * 2 + h], ahi[mt], &blo[pq][h * 2]);
#pragma unroll
                for (int mt = 0; mt < 2; mt++)
#pragma unroll
                    for (int pq = 0; pq < 2; pq++)
#pragma unroll
                        for (int h = 0; h < 2; h++)
                            mma_bf16(c[mt][nh * 4 + pq * 2 + h], alo[mt], &bhi[pq][h * 2]);
            }
        }

        __syncthreads();       // all warps done READING pair p's stages

        // ---- prefetch pair p+2 into pair p's (now-free) stages ----
        if (2 * p + 4 < nkt) {
#pragma unroll
            for (int t2 = 0; t2 < 2; t2++) {
                int tile = 2 * p + 4 + t2;
                uint32_t b = sbase + (uint32_t)(tile & 3) * STAGEB + sdst;
                int ko = tile * 16;
                cp_async16(b,            pAhi + ko);
                cp_async16(b + ARRB,     pAlo + ko);
                cp_async16(b + 2 * ARRB, pBhi + ko);
                cp_async16(b + 3 * ARRB, pBlo + ko);
            }
        }
        CP_COMMIT();           // one group per pair (possibly empty near the end)
    }

    // epilogue
#pragma unroll
    for (int mt = 0; mt < 2; mt++) {
        int row = m0 + wm + mt * 16 + grp;
#pragma unroll
        for (int nt = 0; nt < 8; nt++) {
            int col = n0 + wn + nt * 8 + tig * 2;
            size_t i0 = (size_t)row * N + col;
            size_t i1 = (size_t)(row + 8) * N + col;
            float2 v0 = make_float2(c[mt][nt][0], c[mt][nt][1]);
            float2 v1 = make_float2(c[mt][nt][2], c[mt][nt][3]);
            if (addend) {
                float2 a0 = *(const float2*)(addend + i0);
                float2 a1 = *(const float2*)(addend + i1);
                v0.x += a0.x; v0.y += a0.y;
                v1.x += a1.x; v1.y += a1.y;
            }
            *(float2*)(C + i0) = v0;
            *(float2*)(C + i1) = v1;
        }
    }
}

// ---------------------------------------------------------------------------
// Embedding gather
// ---------------------------------------------------------------------------
__global__ void embed_kernel(const int* __restrict__ ids,
                             const float* __restrict__ embed,
                             float* __restrict__ res) {
    int t = blockIdx.x;
    int id = ids[t];
    const float4* src = (const float4*)(embed + (size_t)id * Hc);
    float4* dst = (float4*)(res + (size_t)t * Hc);
    for (int i = threadIdx.x; i < Hc / 4; i += blockDim.x)
        dst[i] = src[i];
}

// ---------------------------------------------------------------------------
// Fused (optional residual add) + RMSNorm.
// ---------------------------------------------------------------------------
__global__ void addnorm_kernel(float* __restrict__ res,
                               const float* __restrict__ add,
                               const float* __restrict__ w,
                               float* __restrict__ outf,
                               __nv_bfloat16* __restrict__ ohi,
                               __nv_bfloat16* __restrict__ olo) {
    int t = blockIdx.x;
    int tid = threadIdx.x;
    float* rp = res + (size_t)t * Hc;
    float vals[8];
    float ss = 0.f;
#pragma unroll
    for (int i = 0; i < 8; i++) {
        int idx = tid + i * 256;
        float v = rp[idx];
        if (add) { v += add[(size_t)t * Hc + idx]; rp[idx] = v; }
        vals[i] = v;
        ss += v * v;
    }
    __shared__ float warp_s[8];
#pragma unroll
    for (int off = 16; off > 0; off >>= 1)
        ss += __shfl_down_sync(0xffffffff, ss, off);
    if ((tid & 31) == 0) warp_s[tid >> 5] = ss;
    __syncthreads();
    if (tid < 8) {
        float v = warp_s[tid];
#pragma unroll
        for (int off = 4; off > 0; off >>= 1)
            v += __shfl_down_sync(0xff, v, off);
        if (tid == 0) warp_s[0] = v;
    }
    __syncthreads();
    float inv = rsqrtf(warp_s[0] * (1.0f / Hc) + EPSc);
#pragma unroll
    for (int i = 0; i < 8; i++) {
        int idx = tid + i * 256;
        float o = vals[i] * inv * w[idx];
        if (outf) outf[(size_t)t * Hc + idx] = o;
        if (ohi) {
            __nv_bfloat16 h, l;
            split2(o, h, l);
            ohi[(size_t)t * Hc + idx] = h;
            olo[(size_t)t * Hc + idx] = l;
        }
    }
}

// ---------------------------------------------------------------------------
// RoPE + KV scatter (fp32, in-place on qkv)
// ---------------------------------------------------------------------------
__global__ void rope_kernel(float* __restrict__ qkv,
                            const int* __restrict__ pos,
                            float* __restrict__ kc,
                            float* __restrict__ vc) {
    int t = blockIdx.x;
    int b = t / Sc, s = t % Sc;
    int tid = threadIdx.x;
    float p = (float)pos[s];
    const float lt = logf(10000.f) / 32.f;

    for (int w = tid; w < (NHc + NKVc) * 32; w += blockDim.x) {
        int head = w / 32, j = w % 32;
        float ang = p * __expf(-(float)j * lt);
        float c = cosf(ang), sn = sinf(ang);
        if (head < NHc) {
            float* base = qkv + (size_t)t * QKVN + head * HDc;
            float x1 = base[j], x2 = base[j + 32];
            base[j]      = x1 * c - x2 * sn;
            base[j + 32] = x2 * c + x1 * sn;
        } else {
            int hk = head - NHc;
            const float* base = qkv + (size_t)t * QKVN + NHc * HDc + hk * HDc;
            float x1 = base[j], x2 = base[j + 32];
            float* kb = kc + (((size_t)(b * NKVc + hk)) * Sc + s) * HDc;
            kb[j]      = x1 * c - x2 * sn;
            kb[j + 32] = x2 * c + x1 * sn;
        }
    }
    for (int w = tid; w < NKVc * HDc; w += blockDim.x) {
        int hv = w / HDc, d = w % HDc;
        vc[(((size_t)(b * NKVc + hv)) * Sc + s) * HDc + d] =
            qkv[(size_t)t * QKVN + (NHc + NKVc) * HDc + hv * HDc + d];
    }
}

// ---------------------------------------------------------------------------
// Flash attention (causal, fp32). One block = 64 queries of one (b, head).
// Softmax parallelized 4 threads/row. Output split to bf16 hi/lo.
// ---------------------------------------------------------------------------
#define FPAD 68
struct __align__(16) FlashSmem {
    float Qs[64][FPAD];
    float Ks[64][FPAD];
    float Vs[64][FPAD];
    float Ss[64][FPAD];
    float mrow[64];
    float lrow[64];
    float arow[64];
};

__global__ void __launch_bounds__(256)
flash_kernel(const float* __restrict__ qbuf,
             const float* __restrict__ kc,
             const float* __restrict__ vc,
             __nv_bfloat16* __restrict__ ahi,
             __nv_bfloat16* __restrict__ alo) {
    extern __shared__ char smem_raw[];
    FlashSmem& sm = *reinterpret_cast<FlashSmem*>(smem_raw);

    int qb = blockIdx.x;
    int h  = blockIdx.y;
    int b  = blockIdx.z;
    int hkv = h / (NHc / NKVc);
    int tid = threadIdx.x;
    int ty = tid / 16, tx = tid % 16;
    const float scale = 0.125f;

#pragma unroll
    for (int rr = 0; rr < 4; rr++) {
        int row = (tid / 16) + rr * 16;
        int col = (tid % 16) * 4;
        const float* src = qbuf + ((size_t)(b * Sc + qb * 64 + row)) * QKVN + h * HDc + col;
        float4 v = *(const float4*)src;
        sm.Qs[col + 0][row] = v.x * scale;
        sm.Qs[col + 1][row] = v.y * scale;
        sm.Qs[col + 2][row] = v.z * scale;
        sm.Qs[col + 3][row] = v.w * scale;
    }
    if (tid < 64) { sm.mrow[tid] = -1e30f; sm.lrow[tid] = 0.f; }

    float oacc[4][4];
#pragma unroll
    for (int i = 0; i < 4; i++)
#pragma unroll
        for (int j = 0; j < 4; j++) oacc[i][j] = 0.f;

    __syncthreads();

    for (int kb = 0; kb <= qb; kb++) {
#pragma unroll
        for (int rr = 0; rr < 4; rr++) {
            int row = (tid / 16) + rr * 16;
            int col = (tid % 16) * 4;
            size_t kvbase = (((size_t)(b * NKVc + hkv)) * Sc + kb * 64 + row) * HDc + col;
            float4 k4 = *(const float4*)(kc + kvbase);
            sm.Ks[col + 0][row] = k4.x;
            sm.Ks[col + 1][row] = k4.y;
            sm.Ks[col + 2][row] = k4.z;
            sm.Ks[col + 3][row] = k4.w;
            *(float4*)&sm.Vs[row][col] = *(const float4*)(vc + kvbase);
        }
        __syncthreads();

        float sacc[4][4];
#pragma unroll
        for (int i = 0; i < 4; i++)
#pragma unroll
            for (int j = 0; j < 4; j++) sacc[i][j] = 0.f;
#pragma unroll 8
        for (int d = 0; d < 64; d++) {
            float qf[4], kf[4];
            *(float4*)qf = *(const float4*)&sm.Qs[d][ty * 4];
            *(float4*)kf = *(const float4*)&sm.Ks[d][tx * 4];
#pragma unroll
            for (int i = 0; i < 4; i++)
#pragma unroll
                for (int j = 0; j < 4; j++)
                    sacc[i][j] = fmaf(qf[i], kf[j], sacc[i][j]);
        }
        if (kb == qb) {
#pragma unroll
            for (int i = 0; i < 4; i++)
#pragma unroll
                for (int j = 0; j < 4; j++)
                    if (tx * 4 + j > ty * 4 + i) sacc[i][j] = -1e30f;
        }
#pragma unroll
        for (int i = 0; i < 4; i++)
#pragma unroll
            for (int j = 0; j < 4; j++)
                sm.Ss[tx * 4 + j][ty * 4 + i] = sacc[i][j];
        __syncthreads();

        // ---- online softmax: 4 threads per query row ----
        {
            int q = tid >> 2;
            int part = tid & 3;
            float m_old = sm.mrow[q];
            float m = m_old;
#pragma unroll
            for (int i = 0; i < 16; i++)
                m = fmaxf(m, sm.Ss[part + i * 4][q]);
            m = fmaxf(m, __shfl_xor_sync(0xffffffffu, m, 1));
            m = fmaxf(m, __shfl_xor_sync(0xffffffffu, m, 2));
            float ls = 0.f;
#pragma unroll
            for (int i = 0; i < 16; i++) {
                int k = part + i * 4;
                float pv = __expf(sm.Ss[k][q] - m);
                sm.Ss[k][q] = pv;
                ls += pv;
            }
            ls += __shfl_xor_sync(0xffffffffu, ls, 1);
            ls += __shfl_xor_sync(0xffffffffu, ls, 2);
            if (part == 0) {
                float alpha = __expf(m_old - m);
                sm.mrow[q] = m;
                sm.lrow[q] = sm.lrow[q] * alpha + ls;
                sm.arow[q] = alpha;
            }
        }
        __syncthreads();

        float al[4];
#pragma unroll
        for (int i = 0; i < 4; i++) al[i] = sm.arow[ty * 4 + i];
#pragma unroll
        for (int i = 0; i < 4; i++)
#pragma unroll
            for (int j = 0; j < 4; j++) oacc[i][j] *= al[i];
#pragma unroll 8
        for (int k = 0; k < 64; k++) {
            float pf[4], vf[4];
            *(float4*)pf = *(const float4*)&sm.Ss[k][ty * 4];
            *(float4*)vf = *(const float4*)&sm.Vs[k][tx * 4];
#pragma unroll
            for (int i = 0; i < 4; i++)
#pragma unroll
                for (int j = 0; j < 4; j++)
                    oacc[i][j] = fmaf(pf[i], vf[j], oacc[i][j]);
        }
        __syncthreads();
    }

#pragma unroll
    for (int i = 0; i < 4; i++) {
        float inv = 1.0f / sm.lrow[ty * 4 + i];
        int q = qb * 64 + ty * 4 + i;
        size_t base = ((size_t)(b * Sc + q)) * (NHc * HDc) + h * HDc + tx * 4;
#pragma unroll
        for (int j = 0; j < 4; j++) {
            float v = oacc[i][j] * inv;
            __nv_bfloat16 hbit, lbit;
            split2(v, hbit, lbit);
            ahi[base + j] = hbit;
            alo[base + j] = lbit;
        }
    }
}

// ---------------------------------------------------------------------------
// SwiGLU (output split bf16; feeds down GEMM)
// ---------------------------------------------------------------------------
__global__ void swiglu_kernel(const float* __restrict__ gu,
                              __nv_bfloat16* __restrict__ ahi,
                              __nv_bfloat16* __restrict__ alo) {
    size_t e = (size_t)blockIdx.x * blockDim.x + threadIdx.x;
    size_t t = e / Ic;
    size_t i = e % Ic;
    float g = gu[t * GUN + i];
    float u = gu[t * GUN + Ic + i];
    float sig = 1.0f / (1.0f + __expf(-g));
    float v = g * sig * u;
    __nv_bfloat16 h, l;
    split2(v, h, l);
    ahi[e] = h;
    alo[e] = l;
}

// ---------------------------------------------------------------------------
// Launch
// ---------------------------------------------------------------------------
extern "C" void kernel_launch(void* const* d_in, const int* in_sizes, int n_in,
                              void* d_out, int out_size) {
    const int*   input_ids = (const int*)d_in[0];
    const int*   positions = (const int*)d_in[1];
    const float* embed     = (const float*)d_in[2];
    const float* w_qkv     = (const float*)d_in[3];
    const float* w_o       = (const float*)d_in[4];
    const float* w_gate_up = (const float*)d_in[5];
    const float* w_down    = (const float*)d_in[6];
    const float* ln1_w     = (const float*)d_in[7];
    const float* ln2_w     = (const float*)d_in[8];
    const float* norm_w    = (const float*)d_in[9];
    float* out = (float*)d_out;

    float *res, *qkv, *kc, *vc, *gu, *hbuf;
    __nv_bfloat16 *hnh, *hnl, *ath, *atl, *ach, *acl, *wth, *wtl;
    cudaGetSymbolAddress((void**)&res,  g_res);
    cudaGetSymbolAddress((void**)&qkv,  g_qkv);
    cudaGetSymbolAddress((void**)&kc,   g_kc);
    cudaGetSymbolAddress((void**)&vc,   g_vc);
    cudaGetSymbolAddress((void**)&gu,   g_gu);
    cudaGetSymbolAddress((void**)&hbuf, g_h);
    cudaGetSymbolAddress((void**)&hnh,  g_hn_hi);
    cudaGetSymbolAddress((void**)&hnl,  g_hn_lo);
    cudaGetSymbolAddress((void**)&ath,  g_at_hi);
    cudaGetSymbolAddress((void**)&atl,  g_at_lo);
    cudaGetSymbolAddress((void**)&ach,  g_ac_hi);
    cudaGetSymbolAddress((void**)&acl,  g_ac_lo);
    cudaGetSymbolAddress((void**)&wth,  g_wt_hi);
    cudaGetSymbolAddress((void**)&wtl,  g_wt_lo);

    int flash_smem = (int)sizeof(FlashSmem);
    cudaFuncSetAttribute(flash_kernel, cudaFuncAttributeMaxDynamicSharedMemorySize, flash_smem);
    cudaFuncSetAttribute(gemm_bf16x2, cudaFuncAttributeMaxDynamicSharedMemorySize, GEMM_SMEM);

    // fused one-shot weight prep (transpose + bf16x2 split, all 8 matrices)
    prep_weights<<<2 * TILES_PER_LAYER, dim3(32, 8)>>>(
        w_qkv, w_o, w_gate_up, w_down, wth, wtl);

    embed_kernel<<<Tc, 256>>>(input_ids, embed, res);

    for (int l = 0; l < Lc; l++) {
        __nv_bfloat16* wh = wth + (size_t)l * WT_PER_L;
        __nv_bfloat16* wl = wtl + (size_t)l * WT_PER_L;

        addnorm_kernel<<<Tc, 256>>>(res, l == 0 ? nullptr : hbuf,
                                    ln1_w + (size_t)l * Hc, nullptr, hnh, hnl);

        gemm_bf16x2<<<dim3(Tc / 128, QKVN / 128), 256, GEMM_SMEM>>>(
            hnh, hnl, wh + WT_QKV_OFF, wl + WT_QKV_OFF, qkv, nullptr, Tc, QKVN, Hc);

        rope_kernel<<<Tc, 128>>>(qkv, positions, kc, vc);

        flash_kernel<<<dim3(Sc / 64, NHc, Bc), 256, flash_smem>>>(qkv, kc, vc, ath, atl);

        gemm_bf16x2<<<dim3(Tc / 128, Hc / 128), 256, GEMM_SMEM>>>(
            ath, atl, wh + WT_O_OFF, wl + WT_O_OFF, res, res, Tc, Hc, Hc);

        addnorm_kernel<<<Tc, 256>>>(res, nullptr, ln2_w + (size_t)l * Hc, nullptr, hnh, hnl);

        gemm_bf16x2<<<dim3(Tc / 128, GUN / 128), 256, GEMM_SMEM>>>(
            hnh, hnl, wh + WT_GU_OFF, wl + WT_GU_OFF, gu, nullptr, Tc, GUN, Hc);

        swiglu_kernel<<<(Tc * (size_t)Ic) / 256, 256>>>(gu, ach, acl);

        gemm_bf16x2<<<dim3(Tc / 128, Hc / 128), 256, GEMM_SMEM>>>(
            ach, acl, wh + WT_DN_OFF, wl + WT_DN_OFF, hbuf, nullptr, Tc, Hc, Ic);
    }

    addnorm_kernel<<<Tc, 256>>>(res, hbuf, norm_w, out, nullptr, nullptr);
}

// round 8
// speedup vs baseline: 1.4960x; 1.4960x over previous
#include <cuda_runtime.h>
#include <cuda_fp16.h>
#include <math.h>
#include <stdint.h>

// ---------------------------------------------------------------------------
// Model constants
// ---------------------------------------------------------------------------
#define Lc 2
#define Hc 2048
#define NHc 32
#define NKVc 4
#define HDc 64
#define Ic 5632
#define Bc 2
#define Sc 1024
#define Tc (Bc * Sc)                   // 2048 tokens
#define QKVN ((NHc + 2 * NKVc) * HDc)  // 2560
#define GUN (2 * Ic)                   // 11264
#define EPSc 1e-5f
#define WSCALE 64.0f
#define WINV   0.015625f               // 1/64

// ---------------------------------------------------------------------------
// Scratch (static device globals; no allocation allowed)
// ---------------------------------------------------------------------------
__device__ float g_res [Tc * Hc];
__device__ float g_qkv [Tc * QKVN];
__device__ float g_kc  [Bc * NKVc * Sc * HDc];
__device__ float g_vc  [Bc * NKVc * Sc * HDc];
__device__ float g_gu  [(size_t)Tc * GUN];
__device__ float g_h   [Tc * Hc];

// fp16 activations (GEMM A operands)
__device__ __half g_hn [Tc * Hc];
__device__ __half g_at [Tc * Hc];
__device__ __half g_ac [(size_t)Tc * Ic];

// Transposed split weights (x64 scaled, fp16 hi+lo exact 2-term):
// per layer [qkv_t(QKVN,H) | o_t(H,H) | gu_t(GUN,H) | down_t(H,I)]
#define WT_QKV_OFF 0
#define WT_O_OFF   ((size_t)QKVN * Hc)
#define WT_GU_OFF  (WT_O_OFF + (size_t)Hc * Hc)
#define WT_DN_OFF  (WT_GU_OFF + (size_t)GUN * Hc)
#define WT_PER_L   (WT_DN_OFF + (size_t)Hc * Ic)
__device__ __half g_wh[2 * WT_PER_L];
__device__ __half g_wl[2 * WT_PER_L];

// ---------------------------------------------------------------------------
// Helpers
// ---------------------------------------------------------------------------
__device__ __forceinline__ uint32_t smem_u32(const void* p) {
    uint32_t a;
    asm("{ .reg .u64 t; cvta.to.shared.u64 t, %1; cvt.u32.u64 %0, t; }"
        : "=r"(a) : "l"(p));
    return a;
}

__device__ __forceinline__ void cp_async16(uint32_t smem_addr, const void* gptr) {
    asm volatile("cp.async.cg.shared.global [%0], [%1], 16;"
                 :: "r"(smem_addr), "l"(gptr) : "memory");
}
#define CP_COMMIT() asm volatile("cp.async.commit_group;" ::: "memory")
#define CP_WAIT2()  asm volatile("cp.async.wait_group 2;" ::: "memory")

__device__ __forceinline__ void mma_f16(float* d, const uint32_t* a, const uint32_t* b) {
    asm volatile(
        "mma.sync.aligned.m16n8k16.row.col.f32.f16.f16.f32 "
        "{%0,%1,%2,%3}, {%4,%5,%6,%7}, {%8,%9}, {%0,%1,%2,%3};"
        : "+f"(d[0]), "+f"(d[1]), "+f"(d[2]), "+f"(d[3])
        : "r"(a[0]), "r"(a[1]), "r"(a[2]), "r"(a[3]),
          "r"(b[0]), "r"(b[1]));
}

#define LDSM4(R, A) \
    asm volatile("ldmatrix.sync.aligned.m8n8.x4.shared.b16 {%0,%1,%2,%3}, [%4];" \
        : "=r"((R)[0]), "=r"((R)[1]), "=r"((R)[2]), "=r"((R)[3]) : "r"(A))

// ---------------------------------------------------------------------------
// Fused weight prep: transpose + x64 scale + exact fp16 2-term split.
// src[K,N] -> hi/lo[N,K]
// ---------------------------------------------------------------------------
#define TILES_PER_LAYER 43008
__global__ void prep_weights(const float* __restrict__ wqkv,
                             const float* __restrict__ wo,
                             const float* __restrict__ wgu,
                             const float* __restrict__ wdn,
                             __half* __restrict__ wth,
                             __half* __restrict__ wtl) {
    __shared__ float tile[32][33];
    int bid = blockIdx.x;
    int l = 0;
    if (bid >= TILES_PER_LAYER) { l = 1; bid -= TILES_PER_LAYER; }
    size_t loff = (size_t)l * WT_PER_L;

    const float* src;
    __half *hi, *lo;
    int K, N;
    if (bid < 5120) {
        src = wqkv + (size_t)l * Hc * QKVN;
        hi = wth + loff + WT_QKV_OFF; lo = wtl + loff + WT_QKV_OFF;
        K = Hc; N = QKVN;
    } else if (bid < 9216) {
        bid -= 5120;
        src = wo + (size_t)l * Hc * Hc;
        hi = wth + loff + WT_O_OFF; lo = wtl + loff + WT_O_OFF;
        K = Hc; N = Hc;
    } else if (bid < 31744) {
        bid -= 9216;
        src = wgu + (size_t)l * Hc * GUN;
        hi = wth + loff + WT_GU_OFF; lo = wtl + loff + WT_GU_OFF;
        K = Hc; N = GUN;
    } else {
        bid -= 31744;
        src = wdn + (size_t)l * Ic * Hc;
        hi = wth + loff + WT_DN_OFF; lo = wtl + loff + WT_DN_OFF;
        K = Ic; N = Hc;
    }
    int tilesX = N / 32;
    int nb = (bid % tilesX) * 32;
    int kb = (bid / tilesX) * 32;

#pragma unroll
    for (int i = threadIdx.y; i < 32; i += 8)
        tile[i][threadIdx.x] = src[(size_t)(kb + i) * N + nb + threadIdx.x];
    __syncthreads();
#pragma unroll
    for (int i = threadIdx.y; i < 32; i += 8) {
        float v = tile[threadIdx.x][i] * WSCALE;
        __half h = __float2half_rn(v);
        __half lv = __float2half_rn(v - __half2float(h));
        size_t idx = (size_t)(nb + i) * K + kb + threadIdx.x;
        hi[idx] = h;
        lo[idx] = lv;
    }
}

// ---------------------------------------------------------------------------
// fp16 2-term GEMM: C[M,N] = (A_f16[M,K] @ (Whi+Wlo)[N,K]^T) / 64 (+ addend)
// Weights exact (2-term split of 64*W); activations fp16 (2^-12 quantization).
// Block 128x128, BK=16, 256 threads (8 warps, 32x64 warp tiles).
// 4-stage cp.async pipeline (wait_group 2), ldmatrix fragment loads.
// ---------------------------------------------------------------------------
#define RPITCH 48                   // bytes per smem row (16 f16 = 32B + 16B pad)
#define ARRB   (128 * RPITCH)       // 6144 per operand array
#define STAGEB (3 * ARRB)           // 18432 per stage (A, Whi, Wlo)
#define GEMM_SMEM (4 * STAGEB)      // 73728 (4 stages)

__global__ void __launch_bounds__(256, 2)
gemm_f16(const __half* __restrict__ A,
         const __half* __restrict__ Wh,
         const __half* __restrict__ Wl,
         float* __restrict__ C, const float* __restrict__ addend,
         int M, int N, int K) {
    extern __shared__ char smraw[];
    uint32_t sbase = smem_u32(smraw);

    const int tid  = threadIdx.x;
    const int warp = tid >> 5;
    const int lane = tid & 31;
    const int wm   = (warp >> 1) * 32;   // warp M offset
    const int wn   = (warp & 1) * 64;    // warp N offset
    const int grp  = lane >> 2;
    const int tig  = lane & 3;

    const int m0 = blockIdx.x * 128;
    const int n0 = blockIdx.y * 128;

    // ldmatrix lane offsets
    const int li = lane >> 3;            // matrix group 0..3
    const int lr = lane & 7;             // row within matrix
    const uint32_t aoffl = (uint32_t)(((li & 1) * 8 + lr) * RPITCH + (li >> 1) * 16);
    const uint32_t boffl = (uint32_t)(((li >> 1) * 8 + lr) * RPITCH + (li & 1) * 16);

    // cp.async staging: thread covers row r0, 16B half of each array
    const int r0   = tid >> 1;           // 0..127
    const int half = tid & 1;
    const uint32_t sdst = (uint32_t)(r0 * RPITCH + half * 16);
    const __half* pA  = A  + (size_t)(m0 + r0) * K + half * 8;
    const __half* pWh = Wh + (size_t)(n0 + r0) * K + half * 8;
    const __half* pWl = Wl + (size_t)(n0 + r0) * K + half * 8;

    const int nkt = K >> 4;

    float c[2][8][4];
#pragma unroll
    for (int mt = 0; mt < 2; mt++)
#pragma unroll
        for (int nt = 0; nt < 8; nt++)
#pragma unroll
            for (int i = 0; i < 4; i++) c[mt][nt][i] = 0.f;

    // prologue: stage tiles 0..2
#pragma unroll
    for (int s = 0; s < 3; s++) {
        uint32_t b = sbase + (uint32_t)s * STAGEB + sdst;
        int ko = s * 16;
        cp_async16(b,            pA  + ko);
        cp_async16(b + ARRB,     pWh + ko);
        cp_async16(b + 2 * ARRB, pWl + ko);
        CP_COMMIT();
    }

    for (int kt = 0; kt < nkt; kt++) {
        CP_WAIT2();            // tile kt's group complete (own thread)
        __syncthreads();       // all threads' loads of tile kt visible

        uint32_t sb = sbase + (uint32_t)(kt & 3) * STAGEB;

        uint32_t a[2][4];
#pragma unroll
        for (int mt = 0; mt < 2; mt++) {
            uint32_t aaddr = sb + (uint32_t)((wm + mt * 16) * RPITCH) + aoffl;
            LDSM4(a[mt], aaddr);
        }
#pragma unroll
        for (int nh = 0; nh < 2; nh++) {
            uint32_t wh[2][4], wl[2][4];
#pragma unroll
            for (int pq = 0; pq < 2; pq++) {
                uint32_t baddr = sb + ARRB +
                                 (uint32_t)((wn + nh * 32 + pq * 16) * RPITCH) + boffl;
                LDSM4(wh[pq], baddr);
                LDSM4(wl[pq], baddr + ARRB);
            }
            // term-major: A*Whi (16 MMAs), then A*Wlo (16 MMAs)
#pragma unroll
            for (int mt = 0; mt < 2; mt++)
#pragma unroll
                for (int pq = 0; pq < 2; pq++)
#pragma unroll
                    for (int h = 0; h < 2; h++)
                        mma_f16(c[mt][nh * 4 + pq * 2 + h], a[mt], &wh[pq][h * 2]);
#pragma unroll
            for (int mt = 0; mt < 2; mt++)
#pragma unroll
                for (int pq = 0; pq < 2; pq++)
#pragma unroll
                    for (int h = 0; h < 2; h++)
                        mma_f16(c[mt][nh * 4 + pq * 2 + h], a[mt], &wl[pq][h * 2]);
        }

        // prefetch tile kt+3 into stage (kt+3)&3 (stage of kt-1; all warps
        // passed this iteration's barrier, so kt-1 reads are done)
        if (kt + 3 < nkt) {
            uint32_t b = sbase + (uint32_t)((kt + 3) & 3) * STAGEB + sdst;
            int ko = (kt + 3) * 16;
            cp_async16(b,            pA  + ko);
            cp_async16(b + ARRB,     pWh + ko);
            cp_async16(b + 2 * ARRB, pWl + ko);
        }
        CP_COMMIT();           // one group per iteration (possibly empty)
    }

    // epilogue (unscale by 1/64)
#pragma unroll
    for (int mt = 0; mt < 2; mt++) {
        int row = m0 + wm + mt * 16 + grp;
#pragma unroll
        for (int nt = 0; nt < 8; nt++) {
            int col = n0 + wn + nt * 8 + tig * 2;
            size_t i0 = (size_t)row * N + col;
            size_t i1 = (size_t)(row + 8) * N + col;
            float2 v0 = make_float2(c[mt][nt][0] * WINV, c[mt][nt][1] * WINV);
            float2 v1 = make_float2(c[mt][nt][2] * WINV, c[mt][nt][3] * WINV);
            if (addend) {
                float2 a0 = *(const float2*)(addend + i0);
                float2 a1 = *(const float2*)(addend + i1);
                v0.x += a0.x; v0.y += a0.y;
                v1.x += a1.x; v1.y += a1.y;
            }
            *(float2*)(C + i0) = v0;
            *(float2*)(C + i1) = v1;
        }
    }
}

// ---------------------------------------------------------------------------
// Embedding gather
// ---------------------------------------------------------------------------
__global__ void embed_kernel(const int* __restrict__ ids,
                             const float* __restrict__ embed,
                             float* __restrict__ res) {
    int t = blockIdx.x;
    int id = ids[t];
    const float4* src = (const float4*)(embed + (size_t)id * Hc);
    float4* dst = (float4*)(res + (size_t)t * Hc);
    for (int i = threadIdx.x; i < Hc / 4; i += blockDim.x)
        dst[i] = src[i];
}

// ---------------------------------------------------------------------------
// Fused (optional residual add) + RMSNorm. Output fp32 (outf) and/or fp16 (oh).
// ---------------------------------------------------------------------------
__global__ void addnorm_kernel(float* __restrict__ res,
                               const float* __restrict__ add,
                               const float* __restrict__ w,
                               float* __restrict__ outf,
                               __half* __restrict__ oh) {
    int t = blockIdx.x;
    int tid = threadIdx.x;
    float* rp = res + (size_t)t * Hc;
    float vals[8];
    float ss = 0.f;
#pragma unroll
    for (int i = 0; i < 8; i++) {
        int idx = tid + i * 256;
        float v = rp[idx];
        if (add) { v += add[(size_t)t * Hc + idx]; rp[idx] = v; }
        vals[i] = v;
        ss += v * v;
    }
    __shared__ float warp_s[8];
#pragma unroll
    for (int off = 16; off > 0; off >>= 1)
        ss += __shfl_down_sync(0xffffffff, ss, off);
    if ((tid & 31) == 0) warp_s[tid >> 5] = ss;
    __syncthreads();
    if (tid < 8) {
        float v = warp_s[tid];
#pragma unroll
        for (int off = 4; off > 0; off >>= 1)
            v += __shfl_down_sync(0xff, v, off);
        if (tid == 0) warp_s[0] = v;
    }
    __syncthreads();
    float inv = rsqrtf(warp_s[0] * (1.0f / Hc) + EPSc);
#pragma unroll
    for (int i = 0; i < 8; i++) {
        int idx = tid + i * 256;
        float o = vals[i] * inv * w[idx];
        if (outf) outf[(size_t)t * Hc + idx] = o;
        if (oh)   oh[(size_t)t * Hc + idx] = __float2half_rn(o);
    }
}

// ---------------------------------------------------------------------------
// RoPE + KV scatter (fp32, in-place on qkv)
// ---------------------------------------------------------------------------
__global__ void rope_kernel(float* __restrict__ qkv,
                            const int* __restrict__ pos,
                            float* __restrict__ kc,
                            float* __restrict__ vc) {
    int t = blockIdx.x;
    int b = t / Sc, s = t % Sc;
    int tid = threadIdx.x;
    float p = (float)pos[s];
    const float lt = logf(10000.f) / 32.f;

    for (int w = tid; w < (NHc + NKVc) * 32; w += blockDim.x) {
        int head = w / 32, j = w % 32;
        float ang = p * __expf(-(float)j * lt);
        float c = cosf(ang), sn = sinf(ang);
        if (head < NHc) {
            float* base = qkv + (size_t)t * QKVN + head * HDc;
            float x1 = base[j], x2 = base[j + 32];
            base[j]      = x1 * c - x2 * sn;
            base[j + 32] = x2 * c + x1 * sn;
        } else {
            int hk = head - NHc;
            const float* base = qkv + (size_t)t * QKVN + NHc * HDc + hk * HDc;
            float x1 = base[j], x2 = base[j + 32];
            float* kb = kc + (((size_t)(b * NKVc + hk)) * Sc + s) * HDc;
            kb[j]      = x1 * c - x2 * sn;
            kb[j + 32] = x2 * c + x1 * sn;
        }
    }
    for (int w = tid; w < NKVc * HDc; w += blockDim.x) {
        int hv = w / HDc, d = w % HDc;
        vc[(((size_t)(b * NKVc + hv)) * Sc + s) * HDc + d] =
            qkv[(size_t)t * QKVN + (NHc + NKVc) * HDc + hv * HDc + d];
    }
}

// ---------------------------------------------------------------------------
// Flash attention (causal, fp32). One block = 64 queries of one (b, head).
// Softmax parallelized 4 threads/row. Output fp16 (feeds o-proj GEMM).
// ---------------------------------------------------------------------------
#define FPAD 68
struct __align__(16) FlashSmem {
    float Qs[64][FPAD];
    float Ks[64][FPAD];
    float Vs[64][FPAD];
    float Ss[64][FPAD];
    float mrow[64];
    float lrow[64];
    float arow[64];
};

__global__ void __launch_bounds__(256)
flash_kernel(const float* __restrict__ qbuf,
             const float* __restrict__ kc,
             const float* __restrict__ vc,
             __half* __restrict__ aout) {
    extern __shared__ char smem_raw[];
    FlashSmem& sm = *reinterpret_cast<FlashSmem*>(smem_raw);

    int qb = blockIdx.x;
    int h  = blockIdx.y;
    int b  = blockIdx.z;
    int hkv = h / (NHc / NKVc);
    int tid = threadIdx.x;
    int ty = tid / 16, tx = tid % 16;
    const float scale = 0.125f;

#pragma unroll
    for (int rr = 0; rr < 4; rr++) {
        int row = (tid / 16) + rr * 16;
        int col = (tid % 16) * 4;
        const float* src = qbuf + ((size_t)(b * Sc + qb * 64 + row)) * QKVN + h * HDc + col;
        float4 v = *(const float4*)src;
        sm.Qs[col + 0][row] = v.x * scale;
        sm.Qs[col + 1][row] = v.y * scale;
        sm.Qs[col + 2][row] = v.z * scale;
        sm.Qs[col + 3][row] = v.w * scale;
    }
    if (tid < 64) { sm.mrow[tid] = -1e30f; sm.lrow[tid] = 0.f; }

    float oacc[4][4];
#pragma unroll
    for (int i = 0; i < 4; i++)
#pragma unroll
        for (int j = 0; j < 4; j++) oacc[i][j] = 0.f;

    __syncthreads();

    for (int kb = 0; kb <= qb; kb++) {
#pragma unroll
        for (int rr = 0; rr < 4; rr++) {
            int row = (tid / 16) + rr * 16;
            int col = (tid % 16) * 4;
            size_t kvbase = (((size_t)(b * NKVc + hkv)) * Sc + kb * 64 + row) * HDc + col;
            float4 k4 = *(const float4*)(kc + kvbase);
            sm.Ks[col + 0][row] = k4.x;
            sm.Ks[col + 1][row] = k4.y;
            sm.Ks[col + 2][row] = k4.z;
            sm.Ks[col + 3][row] = k4.w;
            *(float4*)&sm.Vs[row][col] = *(const float4*)(vc + kvbase);
        }
        __syncthreads();

        float sacc[4][4];
#pragma unroll
        for (int i = 0; i < 4; i++)
#pragma unroll
            for (int j = 0; j < 4; j++) sacc[i][j] = 0.f;
#pragma unroll 8
        for (int d = 0; d < 64; d++) {
            float qf[4], kf[4];
            *(float4*)qf = *(const float4*)&sm.Qs[d][ty * 4];
            *(float4*)kf = *(const float4*)&sm.Ks[d][tx * 4];
#pragma unroll
            for (int i = 0; i < 4; i++)
#pragma unroll
                for (int j = 0; j < 4; j++)
                    sacc[i][j] = fmaf(qf[i], kf[j], sacc[i][j]);
        }
        if (kb == qb) {
#pragma unroll
            for (int i = 0; i < 4; i++)
#pragma unroll
                for (int j = 0; j < 4; j++)
                    if (tx * 4 + j > ty * 4 + i) sacc[i][j] = -1e30f;
        }
#pragma unroll
        for (int i = 0; i < 4; i++)
#pragma unroll
            for (int j = 0; j < 4; j++)
                sm.Ss[tx * 4 + j][ty * 4 + i] = sacc[i][j];
        __syncthreads();

        // ---- online softmax: 4 threads per query row ----
        {
            int q = tid >> 2;
            int part = tid & 3;
            float m_old = sm.mrow[q];
            float m = m_old;
#pragma unroll
            for (int i = 0; i < 16; i++)
                m = fmaxf(m, sm.Ss[part + i * 4][q]);
            m = fmaxf(m, __shfl_xor_sync(0xffffffffu, m, 1));
            m = fmaxf(m, __shfl_xor_sync(0xffffffffu, m, 2));
            float ls = 0.f;
#pragma unroll
            for (int i = 0; i < 16; i++) {
                int k = part + i * 4;
                float pv = __expf(sm.Ss[k][q] - m);
                sm.Ss[k][q] = pv;
                ls += pv;
            }
            ls += __shfl_xor_sync(0xffffffffu, ls, 1);
            ls += __shfl_xor_sync(0xffffffffu, ls, 2);
            if (part == 0) {
                float alpha = __expf(m_old - m);
                sm.mrow[q] = m;
                sm.lrow[q] = sm.lrow[q] * alpha + ls;
                sm.arow[q] = alpha;
            }
        }
        __syncthreads();

        float al[4];
#pragma unroll
        for (int i = 0; i < 4; i++) al[i] = sm.arow[ty * 4 + i];
#pragma unroll
        for (int i = 0; i < 4; i++)
#pragma unroll
            for (int j = 0; j < 4; j++) oacc[i][j] *= al[i];
#pragma unroll 8
        for (int k = 0; k < 64; k++) {
            float pf[4], vf[4];
            *(float4*)pf = *(const float4*)&sm.Ss[k][ty * 4];
            *(float4*)vf = *(const float4*)&sm.Vs[k][tx * 4];
#pragma unroll
            for (int i = 0; i < 4; i++)
#pragma unroll
                for (int j = 0; j < 4; j++)
                    oacc[i][j] = fmaf(pf[i], vf[j], oacc[i][j]);
        }
        __syncthreads();
    }

#pragma unroll
    for (int i = 0; i < 4; i++) {
        float inv = 1.0f / sm.lrow[ty * 4 + i];
        int q = qb * 64 + ty * 4 + i;
        size_t base = ((size_t)(b * Sc + q)) * (NHc * HDc) + h * HDc + tx * 4;
#pragma unroll
        for (int j = 0; j < 4; j++)
            aout[base + j] = __float2half_rn(oacc[i][j] * inv);
    }
}

// ---------------------------------------------------------------------------
// SwiGLU (output fp16; feeds down GEMM)
// ---------------------------------------------------------------------------
__global__ void swiglu_kernel(const float* __restrict__ gu,
                              __half* __restrict__ act) {
    size_t e = (size_t)blockIdx.x * blockDim.x + threadIdx.x;
    size_t t = e / Ic;
    size_t i = e % Ic;
    float g = gu[t * GUN + i];
    float u = gu[t * GUN + Ic + i];
    float sig = 1.0f / (1.0f + __expf(-g));
    act[e] = __float2half_rn(g * sig * u);
}

// ---------------------------------------------------------------------------
// Launch
// ---------------------------------------------------------------------------
extern "C" void kernel_launch(void* const* d_in, const int* in_sizes, int n_in,
                              void* d_out, int out_size) {
    const int*   input_ids = (const int*)d_in[0];
    const int*   positions = (const int*)d_in[1];
    const float* embed     = (const float*)d_in[2];
    const float* w_qkv     = (const float*)d_in[3];
    const float* w_o       = (const float*)d_in[4];
    const float* w_gate_up = (const float*)d_in[5];
    const float* w_down    = (const float*)d_in[6];
    const float* ln1_w     = (const float*)d_in[7];
    const float* ln2_w     = (const float*)d_in[8];
    const float* norm_w    = (const float*)d_in[9];
    float* out = (float*)d_out;

    float *res, *qkv, *kc, *vc, *gu, *hbuf;
    __half *hn, *at, *ac, *wh, *wl;
    cudaGetSymbolAddress((void**)&res,  g_res);
    cudaGetSymbolAddress((void**)&qkv,  g_qkv);
    cudaGetSymbolAddress((void**)&kc,   g_kc);
    cudaGetSymbolAddress((void**)&vc,   g_vc);
    cudaGetSymbolAddress((void**)&gu,   g_gu);
    cudaGetSymbolAddress((void**)&hbuf, g_h);
    cudaGetSymbolAddress((void**)&hn,   g_hn);
    cudaGetSymbolAddress((void**)&at,   g_at);
    cudaGetSymbolAddress((void**)&ac,   g_ac);
    cudaGetSymbolAddress((void**)&wh,   g_wh);
    cudaGetSymbolAddress((void**)&wl,   g_wl);

    int flash_smem = (int)sizeof(FlashSmem);
    cudaFuncSetAttribute(flash_kernel, cudaFuncAttributeMaxDynamicSharedMemorySize, flash_smem);
    cudaFuncSetAttribute(gemm_f16, cudaFuncAttributeMaxDynamicSharedMemorySize, GEMM_SMEM);

    // fused one-shot weight prep (transpose + x64 scale + fp16 2-term split)
    prep_weights<<<2 * TILES_PER_LAYER, dim3(32, 8)>>>(
        w_qkv, w_o, w_gate_up, w_down, wh, wl);

    embed_kernel<<<Tc, 256>>>(input_ids, embed, res);

    for (int l = 0; l < Lc; l++) {
        __half* whl = wh + (size_t)l * WT_PER_L;
        __half* wll = wl + (size_t)l * WT_PER_L;

        addnorm_kernel<<<Tc, 256>>>(res, l == 0 ? nullptr : hbuf,
                                    ln1_w + (size_t)l * Hc, nullptr, hn);

        gemm_f16<<<dim3(Tc / 128, QKVN / 128), 256, GEMM_SMEM>>>(
            hn, whl + WT_QKV_OFF, wll + WT_QKV_OFF, qkv, nullptr, Tc, QKVN, Hc);

        rope_kernel<<<Tc, 128>>>(qkv, positions, kc, vc);

        flash_kernel<<<dim3(Sc / 64, NHc, Bc), 256, flash_smem>>>(qkv, kc, vc, at);

        gemm_f16<<<dim3(Tc / 128, Hc / 128), 256, GEMM_SMEM>>>(
            at, whl + WT_O_OFF, wll + WT_O_OFF, res, res, Tc, Hc, Hc);

        addnorm_kernel<<<Tc, 256>>>(res, nullptr, ln2_w + (size_t)l * Hc, nullptr, hn);

        gemm_f16<<<dim3(Tc / 128, GUN / 128), 256, GEMM_SMEM>>>(
            hn, whl + WT_GU_OFF, wll + WT_GU_OFF, gu, nullptr, Tc, GUN, Hc);

        swiglu_kernel<<<(Tc * (size_t)Ic) / 256, 256>>>(gu, ac);

        gemm_f16<<<dim3(Tc / 128, Hc / 128), 256, GEMM_SMEM>>>(
            ac, whl + WT_DN_OFF, wll + WT_DN_OFF, hbuf, nullptr, Tc, Hc, Ic);
    }

    addnorm_kernel<<<Tc, 256>>>(res, hbuf, norm_w, out, nullptr);
}

// round 9
// speedup vs baseline: 1.5201x; 1.0161x over previous
#include <cuda_runtime.h>
#include <cuda_fp16.h>
#include <math.h>
#include <stdint.h>

// ---------------------------------------------------------------------------
// Model constants
// ---------------------------------------------------------------------------
#define Lc 2
#define Hc 2048
#define NHc 32
#define NKVc 4
#define HDc 64
#define Ic 5632
#define Bc 2
#define Sc 1024
#define Tc (Bc * Sc)                   // 2048 tokens
#define QKVN ((NHc + 2 * NKVc) * HDc)  // 2560
#define GUN (2 * Ic)                   // 11264
#define EPSc 1e-5f
#define WSCALE 64.0f
#define WINV   0.015625f               // 1/64

// ---------------------------------------------------------------------------
// Scratch (static device globals; no allocation allowed)
// ---------------------------------------------------------------------------
__device__ float g_res [Tc * Hc];
__device__ float g_qkv [Tc * QKVN];
__device__ float g_kc  [Bc * NKVc * Sc * HDc];
__device__ float g_vc  [Bc * NKVc * Sc * HDc];

// fp16 activations (GEMM A operands)
__device__ __half g_hn [Tc * Hc];
__device__ __half g_at [Tc * Hc];
__device__ __half g_ac [(size_t)Tc * Ic];

// Transposed split weights (x64 scaled, fp16 hi+lo exact 2-term):
// per layer [qkv_t(QKVN,H) | o_t(H,H) | gu_t(GUN,H, gate/up interleaved) | down_t(H,I)]
#define WT_QKV_OFF 0
#define WT_O_OFF   ((size_t)QKVN * Hc)
#define WT_GU_OFF  (WT_O_OFF + (size_t)Hc * Hc)
#define WT_DN_OFF  (WT_GU_OFF + (size_t)GUN * Hc)
#define WT_PER_L   (WT_DN_OFF + (size_t)Hc * Ic)
__device__ __half g_wh[2 * WT_PER_L];
__device__ __half g_wl[2 * WT_PER_L];

// ---------------------------------------------------------------------------
// Helpers
// ---------------------------------------------------------------------------
__device__ __forceinline__ uint32_t smem_u32(const void* p) {
    uint32_t a;
    asm("{ .reg .u64 t; cvta.to.shared.u64 t, %1; cvt.u32.u64 %0, t; }"
        : "=r"(a) : "l"(p));
    return a;
}

__device__ __forceinline__ void cp_async16(uint32_t smem_addr, const void* gptr) {
    asm volatile("cp.async.cg.shared.global [%0], [%1], 16;"
                 :: "r"(smem_addr), "l"(gptr) : "memory");
}
#define CP_COMMIT() asm volatile("cp.async.commit_group;" ::: "memory")
#define CP_WAIT2()  asm volatile("cp.async.wait_group 2;" ::: "memory")

__device__ __forceinline__ void mma_f16(float* d, const uint32_t* a, const uint32_t* b) {
    asm volatile(
        "mma.sync.aligned.m16n8k16.row.col.f32.f16.f16.f32 "
        "{%0,%1,%2,%3}, {%4,%5,%6,%7}, {%8,%9}, {%0,%1,%2,%3};"
        : "+f"(d[0]), "+f"(d[1]), "+f"(d[2]), "+f"(d[3])
        : "r"(a[0]), "r"(a[1]), "r"(a[2]), "r"(a[3]),
          "r"(b[0]), "r"(b[1]));
}

#define LDSM4(R, A) \
    asm volatile("ldmatrix.sync.aligned.m8n8.x4.shared.b16 {%0,%1,%2,%3}, [%4];" \
        : "=r"((R)[0]), "=r"((R)[1]), "=r"((R)[2]), "=r"((R)[3]) : "r"(A))

// ---------------------------------------------------------------------------
// Fused weight prep: transpose + x64 scale + exact fp16 2-term split.
// src[K,N] -> hi/lo[N,K].  For the gate_up matrix the destination rows are
// interleaved (gate i -> 2i, up i -> 2i+1) so the GU GEMM epilogue holds each
// (gate, up) pair in adjacent output columns.
// ---------------------------------------------------------------------------
#define TILES_PER_LAYER 43008
__global__ void prep_weights(const float* __restrict__ wqkv,
                             const float* __restrict__ wo,
                             const float* __restrict__ wgu,
                             const float* __restrict__ wdn,
                             __half* __restrict__ wth,
                             __half* __restrict__ wtl) {
    __shared__ float tile[32][33];
    int bid = blockIdx.x;
    int l = 0;
    if (bid >= TILES_PER_LAYER) { l = 1; bid -= TILES_PER_LAYER; }
    size_t loff = (size_t)l * WT_PER_L;

    const float* src;
    __half *hi, *lo;
    int K, N;
    int gu_mode = 0;
    if (bid < 5120) {
        src = wqkv + (size_t)l * Hc * QKVN;
        hi = wth + loff + WT_QKV_OFF; lo = wtl + loff + WT_QKV_OFF;
        K = Hc; N = QKVN;
    } else if (bid < 9216) {
        bid -= 5120;
        src = wo + (size_t)l * Hc * Hc;
        hi = wth + loff + WT_O_OFF; lo = wtl + loff + WT_O_OFF;
        K = Hc; N = Hc;
    } else if (bid < 31744) {
        bid -= 9216;
        src = wgu + (size_t)l * Hc * GUN;
        hi = wth + loff + WT_GU_OFF; lo = wtl + loff + WT_GU_OFF;
        K = Hc; N = GUN;
        gu_mode = 1;
    } else {
        bid -= 31744;
        src = wdn + (size_t)l * Ic * Hc;
        hi = wth + loff + WT_DN_OFF; lo = wtl + loff + WT_DN_OFF;
        K = Ic; N = Hc;
    }
    int tilesX = N / 32;
    int nb = (bid % tilesX) * 32;
    int kb = (bid / tilesX) * 32;

#pragma unroll
    for (int i = threadIdx.y; i < 32; i += 8)
        tile[i][threadIdx.x] = src[(size_t)(kb + i) * N + nb + threadIdx.x];
    __syncthreads();
#pragma unroll
    for (int i = threadIdx.y; i < 32; i += 8) {
        float v = tile[threadIdx.x][i] * WSCALE;
        __half h = __float2half_rn(v);
        __half lv = __float2half_rn(v - __half2float(h));
        int col = nb + i;
        if (gu_mode) col = (col < Ic) ? (2 * col) : (2 * (col - Ic) + 1);
        size_t idx = (size_t)col * K + kb + threadIdx.x;
        hi[idx] = h;
        lo[idx] = lv;
    }
}

// ---------------------------------------------------------------------------
// fp16 2-term GEMM: C[M,N] = (A_f16[M,K] @ (Whi+Wlo)[N,K]^T) / 64 (+ addend)
// If actout != nullptr: columns are interleaved (gate, up) pairs; epilogue
// computes silu(gate)*up per pair and writes fp16 to actout[M, N/2].
// Block 128x128, BK=16, 256 threads (8 warps, 32x64 warp tiles).
// 4-stage cp.async pipeline (wait_group 2), ldmatrix fragment loads.
// ---------------------------------------------------------------------------
#define RPITCH 48                   // bytes per smem row (16 f16 = 32B + 16B pad)
#define ARRB   (128 * RPITCH)       // 6144 per operand array
#define STAGEB (3 * ARRB)           // 18432 per stage (A, Whi, Wlo)
#define GEMM_SMEM (4 * STAGEB)      // 73728 (4 stages)

__global__ void __launch_bounds__(256, 2)
gemm_f16(const __half* __restrict__ A,
         const __half* __restrict__ Wh,
         const __half* __restrict__ Wl,
         float* __restrict__ C, const float* __restrict__ addend,
         __half* __restrict__ actout,
         int M, int N, int K) {
    extern __shared__ char smraw[];
    uint32_t sbase = smem_u32(smraw);

    const int tid  = threadIdx.x;
    const int warp = tid >> 5;
    const int lane = tid & 31;
    const int wm   = (warp >> 1) * 32;   // warp M offset
    const int wn   = (warp & 1) * 64;    // warp N offset
    const int grp  = lane >> 2;
    const int tig  = lane & 3;

    const int m0 = blockIdx.x * 128;
    const int n0 = blockIdx.y * 128;

    // ldmatrix lane offsets
    const int li = lane >> 3;            // matrix group 0..3
    const int lr = lane & 7;             // row within matrix
    const uint32_t aoffl = (uint32_t)(((li & 1) * 8 + lr) * RPITCH + (li >> 1) * 16);
    const uint32_t boffl = (uint32_t)(((li >> 1) * 8 + lr) * RPITCH + (li & 1) * 16);

    // cp.async staging: thread covers row r0, 16B half of each array
    const int r0   = tid >> 1;           // 0..127
    const int half = tid & 1;
    const uint32_t sdst = (uint32_t)(r0 * RPITCH + half * 16);
    const __half* pA  = A  + (size_t)(m0 + r0) * K + half * 8;
    const __half* pWh = Wh + (size_t)(n0 + r0) * K + half * 8;
    const __half* pWl = Wl + (size_t)(n0 + r0) * K + half * 8;

    const int nkt = K >> 4;

    float c[2][8][4];
#pragma unroll
    for (int mt = 0; mt < 2; mt++)
#pragma unroll
        for (int nt = 0; nt < 8; nt++)
#pragma unroll
            for (int i = 0; i < 4; i++) c[mt][nt][i] = 0.f;

    // prologue: stage tiles 0..2
#pragma unroll
    for (int s = 0; s < 3; s++) {
        uint32_t b = sbase + (uint32_t)s * STAGEB + sdst;
        int ko = s * 16;
        cp_async16(b,            pA  + ko);
        cp_async16(b + ARRB,     pWh + ko);
        cp_async16(b + 2 * ARRB, pWl + ko);
        CP_COMMIT();
    }

    for (int kt = 0; kt < nkt; kt++) {
        CP_WAIT2();            // tile kt's group complete (own thread)
        __syncthreads();       // all threads' loads of tile kt visible

        uint32_t sb = sbase + (uint32_t)(kt & 3) * STAGEB;

        uint32_t a[2][4];
#pragma unroll
        for (int mt = 0; mt < 2; mt++) {
            uint32_t aaddr = sb + (uint32_t)((wm + mt * 16) * RPITCH) + aoffl;
            LDSM4(a[mt], aaddr);
        }
#pragma unroll
        for (int nh = 0; nh < 2; nh++) {
            uint32_t wh[2][4], wl[2][4];
#pragma unroll
            for (int pq = 0; pq < 2; pq++) {
                uint32_t baddr = sb + ARRB +
                                 (uint32_t)((wn + nh * 32 + pq * 16) * RPITCH) + boffl;
                LDSM4(wh[pq], baddr);
                LDSM4(wl[pq], baddr + ARRB);
            }
            // term-major: A*Whi (16 MMAs), then A*Wlo (16 MMAs)
#pragma unroll
            for (int mt = 0; mt < 2; mt++)
#pragma unroll
                for (int pq = 0; pq < 2; pq++)
#pragma unroll
                    for (int h = 0; h < 2; h++)
                        mma_f16(c[mt][nh * 4 + pq * 2 + h], a[mt], &wh[pq][h * 2]);
#pragma unroll
            for (int mt = 0; mt < 2; mt++)
#pragma unroll
                for (int pq = 0; pq < 2; pq++)
#pragma unroll
                    for (int h = 0; h < 2; h++)
                        mma_f16(c[mt][nh * 4 + pq * 2 + h], a[mt], &wl[pq][h * 2]);
        }

        // prefetch tile kt+3 into stage (kt+3)&3 (stage of kt-1; all warps
        // passed this iteration's barrier, so kt-1 reads are done)
        if (kt + 3 < nkt) {
            uint32_t b = sbase + (uint32_t)((kt + 3) & 3) * STAGEB + sdst;
            int ko = (kt + 3) * 16;
            cp_async16(b,            pA  + ko);
            cp_async16(b + ARRB,     pWh + ko);
            cp_async16(b + 2 * ARRB, pWl + ko);
        }
        CP_COMMIT();           // one group per iteration (possibly empty)
    }

    // epilogue (unscale by 1/64)
    if (actout) {
        // interleaved (gate, up) pairs: col tig*2 = gate, tig*2+1 = up
#pragma unroll
        for (int mt = 0; mt < 2; mt++) {
            int row = m0 + wm + mt * 16 + grp;
#pragma unroll
            for (int nt = 0; nt < 8; nt++) {
                int col = n0 + wn + nt * 8 + tig * 2;
                int pair = col >> 1;
                {
                    float g = c[mt][nt][0] * WINV;
                    float u = c[mt][nt][1] * WINV;
                    float sig = 1.0f / (1.0f + __expf(-g));
                    actout[(size_t)row * Ic + pair] = __float2half_rn(g * sig * u);
                }
                {
                    float g = c[mt][nt][2] * WINV;
                    float u = c[mt][nt][3] * WINV;
                    float sig = 1.0f / (1.0f + __expf(-g));
                    actout[(size_t)(row + 8) * Ic + pair] = __float2half_rn(g * sig * u);
                }
            }
        }
    } else {
#pragma unroll
        for (int mt = 0; mt < 2; mt++) {
            int row = m0 + wm + mt * 16 + grp;
#pragma unroll
            for (int nt = 0; nt < 8; nt++) {
                int col = n0 + wn + nt * 8 + tig * 2;
                size_t i0 = (size_t)row * N + col;
                size_t i1 = (size_t)(row + 8) * N + col;
                float2 v0 = make_float2(c[mt][nt][0] * WINV, c[mt][nt][1] * WINV);
                float2 v1 = make_float2(c[mt][nt][2] * WINV, c[mt][nt][3] * WINV);
                if (addend) {
                    float2 a0 = *(const float2*)(addend + i0);
                    float2 a1 = *(const float2*)(addend + i1);
                    v0.x += a0.x; v0.y += a0.y;
                    v1.x += a1.x; v1.y += a1.y;
                }
                *(float2*)(C + i0) = v0;
                *(float2*)(C + i1) = v1;
            }
        }
    }
}

// ---------------------------------------------------------------------------
// Embedding gather
// ---------------------------------------------------------------------------
__global__ void embed_kernel(const int* __restrict__ ids,
                             const float* __restrict__ embed,
                             float* __restrict__ res) {
    int t = blockIdx.x;
    int id = ids[t];
    const float4* src = (const float4*)(embed + (size_t)id * Hc);
    float4* dst = (float4*)(res + (size_t)t * Hc);
    for (int i = threadIdx.x; i < Hc / 4; i += blockDim.x)
        dst[i] = src[i];
}

// ---------------------------------------------------------------------------
// RMSNorm (residual already complete in res). Output fp32 and/or fp16.
// ---------------------------------------------------------------------------
__global__ void addnorm_kernel(const float* __restrict__ res,
                               const float* __restrict__ w,
                               float* __restrict__ outf,
                               __half* __restrict__ oh) {
    int t = blockIdx.x;
    int tid = threadIdx.x;
    const float* rp = res + (size_t)t * Hc;
    float vals[8];
    float ss = 0.f;
#pragma unroll
    for (int i = 0; i < 8; i++) {
        int idx = tid + i * 256;
        float v = rp[idx];
        vals[i] = v;
        ss += v * v;
    }
    __shared__ float warp_s[8];
#pragma unroll
    for (int off = 16; off > 0; off >>= 1)
        ss += __shfl_down_sync(0xffffffff, ss, off);
    if ((tid & 31) == 0) warp_s[tid >> 5] = ss;
    __syncthreads();
    if (tid < 8) {
        float v = warp_s[tid];
#pragma unroll
        for (int off = 4; off > 0; off >>= 1)
            v += __shfl_down_sync(0xff, v, off);
        if (tid == 0) warp_s[0] = v;
    }
    __syncthreads();
    float inv = rsqrtf(warp_s[0] * (1.0f / Hc) + EPSc);
#pragma unroll
    for (int i = 0; i < 8; i++) {
        int idx = tid + i * 256;
        float o = vals[i] * inv * w[idx];
        if (outf) outf[(size_t)t * Hc + idx] = o;
        if (oh)   oh[(size_t)t * Hc + idx] = __float2half_rn(o);
    }
}

// ---------------------------------------------------------------------------
// RoPE + KV scatter (fp32, in-place on qkv)
// ---------------------------------------------------------------------------
__global__ void rope_kernel(float* __restrict__ qkv,
                            const int* __restrict__ pos,
                            float* __restrict__ kc,
                            float* __restrict__ vc) {
    int t = blockIdx.x;
    int b = t / Sc, s = t % Sc;
    int tid = threadIdx.x;
    float p = (float)pos[s];
    const float lt = logf(10000.f) / 32.f;

    for (int w = tid; w < (NHc + NKVc) * 32; w += blockDim.x) {
        int head = w / 32, j = w % 32;
        float ang = p * __expf(-(float)j * lt);
        float c = cosf(ang), sn = sinf(ang);
        if (head < NHc) {
            float* base = qkv + (size_t)t * QKVN + head * HDc;
            float x1 = base[j], x2 = base[j + 32];
            base[j]      = x1 * c - x2 * sn;
            base[j + 32] = x2 * c + x1 * sn;
        } else {
            int hk = head - NHc;
            const float* base = qkv + (size_t)t * QKVN + NHc * HDc + hk * HDc;
            float x1 = base[j], x2 = base[j + 32];
            float* kb = kc + (((size_t)(b * NKVc + hk)) * Sc + s) * HDc;
            kb[j]      = x1 * c - x2 * sn;
            kb[j + 32] = x2 * c + x1 * sn;
        }
    }
    for (int w = tid; w < NKVc * HDc; w += blockDim.x) {
        int hv = w / HDc, d = w % HDc;
        vc[(((size_t)(b * NKVc + hv)) * Sc + s) * HDc + d] =
            qkv[(size_t)t * QKVN + (NHc + NKVc) * HDc + hv * HDc + d];
    }
}

// ---------------------------------------------------------------------------
// Flash attention (causal, fp32). One block = 64 queries of one (b, head).
// Softmax parallelized 4 threads/row. Output fp16 (feeds o-proj GEMM).
// ---------------------------------------------------------------------------
#define FPAD 68
struct __align__(16) FlashSmem {
    float Qs[64][FPAD];
    float Ks[64][FPAD];
    float Vs[64][FPAD];
    float Ss[64][FPAD];
    float mrow[64];
    float lrow[64];
    float arow[64];
};

__global__ void __launch_bounds__(256)
flash_kernel(const float* __restrict__ qbuf,
             const float* __restrict__ kc,
             const float* __restrict__ vc,
             __half* __restrict__ aout) {
    extern __shared__ char smem_raw[];
    FlashSmem& sm = *reinterpret_cast<FlashSmem*>(smem_raw);

    int qb = blockIdx.x;
    int h  = blockIdx.y;
    int b  = blockIdx.z;
    int hkv = h / (NHc / NKVc);
    int tid = threadIdx.x;
    int ty = tid / 16, tx = tid % 16;
    const float scale = 0.125f;

#pragma unroll
    for (int rr = 0; rr < 4; rr++) {
        int row = (tid / 16) + rr * 16;
        int col = (tid % 16) * 4;
        const float* src = qbuf + ((size_t)(b * Sc + qb * 64 + row)) * QKVN + h * HDc + col;
        float4 v = *(const float4*)src;
        sm.Qs[col + 0][row] = v.x * scale;
        sm.Qs[col + 1][row] = v.y * scale;
        sm.Qs[col + 2][row] = v.z * scale;
        sm.Qs[col + 3][row] = v.w * scale;
    }
    if (tid < 64) { sm.mrow[tid] = -1e30f; sm.lrow[tid] = 0.f; }

    float oacc[4][4];
#pragma unroll
    for (int i = 0; i < 4; i++)
#pragma unroll
        for (int j = 0; j < 4; j++) oacc[i][j] = 0.f;

    __syncthreads();

    for (int kb = 0; kb <= qb; kb++) {
#pragma unroll
        for (int rr = 0; rr < 4; rr++) {
            int row = (tid / 16) + rr * 16;
            int col = (tid % 16) * 4;
            size_t kvbase = (((size_t)(b * NKVc + hkv)) * Sc + kb * 64 + row) * HDc + col;
            float4 k4 = *(const float4*)(kc + kvbase);
            sm.Ks[col + 0][row] = k4.x;
            sm.Ks[col + 1][row] = k4.y;
            sm.Ks[col + 2][row] = k4.z;
            sm.Ks[col + 3][row] = k4.w;
            *(float4*)&sm.Vs[row][col] = *(const float4*)(vc + kvbase);
        }
        __syncthreads();

        float sacc[4][4];
#pragma unroll
        for (int i = 0; i < 4; i++)
#pragma unroll
            for (int j = 0; j < 4; j++) sacc[i][j] = 0.f;
#pragma unroll 8
        for (int d = 0; d < 64; d++) {
            float qf[4], kf[4];
            *(float4*)qf = *(const float4*)&sm.Qs[d][ty * 4];
            *(float4*)kf = *(const float4*)&sm.Ks[d][tx * 4];
#pragma unroll
            for (int i = 0; i < 4; i++)
#pragma unroll
                for (int j = 0; j < 4; j++)
                    sacc[i][j] = fmaf(qf[i], kf[j], sacc[i][j]);
        }
        if (kb == qb) {
#pragma unroll
            for (int i = 0; i < 4; i++)
#pragma unroll
                for (int j = 0; j < 4; j++)
                    if (tx * 4 + j > ty * 4 + i) sacc[i][j] = -1e30f;
        }
#pragma unroll
        for (int i = 0; i < 4; i++)
#pragma unroll
            for (int j = 0; j < 4; j++)
                sm.Ss[tx * 4 + j][ty * 4 + i] = sacc[i][j];
        __syncthreads();

        // ---- online softmax: 4 threads per query row ----
        {
            int q = tid >> 2;
            int part = tid & 3;
            float m_old = sm.mrow[q];
            float m = m_old;
#pragma unroll
            for (int i = 0; i < 16; i++)
                m = fmaxf(m, sm.Ss[part + i * 4][q]);
            m = fmaxf(m, __shfl_xor_sync(0xffffffffu, m, 1));
            m = fmaxf(m, __shfl_xor_sync(0xffffffffu, m, 2));
            float ls = 0.f;
#pragma unroll
            for (int i = 0; i < 16; i++) {
                int k = part + i * 4;
                float pv = __expf(sm.Ss[k][q] - m);
                sm.Ss[k][q] = pv;
                ls += pv;
            }
            ls += __shfl_xor_sync(0xffffffffu, ls, 1);
            ls += __shfl_xor_sync(0xffffffffu, ls, 2);
            if (part == 0) {
                float alpha = __expf(m_old - m);
                sm.mrow[q] = m;
                sm.lrow[q] = sm.lrow[q] * alpha + ls;
                sm.arow[q] = alpha;
            }
        }
        __syncthreads();

        float al[4];
#pragma unroll
        for (int i = 0; i < 4; i++) al[i] = sm.arow[ty * 4 + i];
#pragma unroll
        for (int i = 0; i < 4; i++)
#pragma unroll
            for (int j = 0; j < 4; j++) oacc[i][j] *= al[i];
#pragma unroll 8
        for (int k = 0; k < 64; k++) {
            float pf[4], vf[4];
            *(float4*)pf = *(const float4*)&sm.Ss[k][ty * 4];
            *(float4*)vf = *(const float4*)&sm.Vs[k][tx * 4];
#pragma unroll
            for (int i = 0; i < 4; i++)
#pragma unroll
                for (int j = 0; j < 4; j++)
                    oacc[i][j] = fmaf(pf[i], vf[j], oacc[i][j]);
        }
        __syncthreads();
    }

#pragma unroll
    for (int i = 0; i < 4; i++) {
        float inv = 1.0f / sm.lrow[ty * 4 + i];
        int q = qb * 64 + ty * 4 + i;
        size_t base = ((size_t)(b * Sc + q)) * (NHc * HDc) + h * HDc + tx * 4;
#pragma unroll
        for (int j = 0; j < 4; j++)
            aout[base + j] = __float2half_rn(oacc[i][j] * inv);
    }
}

// ---------------------------------------------------------------------------
// Launch
// ---------------------------------------------------------------------------
extern "C" void kernel_launch(void* const* d_in, const int* in_sizes, int n_in,
                              void* d_out, int out_size) {
    const int*   input_ids = (const int*)d_in[0];
    const int*   positions = (const int*)d_in[1];
    const float* embed     = (const float*)d_in[2];
    const float* w_qkv     = (const float*)d_in[3];
    const float* w_o       = (const float*)d_in[4];
    const float* w_gate_up = (const float*)d_in[5];
    const float* w_down    = (const float*)d_in[6];
    const float* ln1_w     = (const float*)d_in[7];
    const float* ln2_w     = (const float*)d_in[8];
    const float* norm_w    = (const float*)d_in[9];
    float* out = (float*)d_out;

    float *res, *qkv, *kc, *vc;
    __half *hn, *at, *ac, *wh, *wl;
    cudaGetSymbolAddress((void**)&res,  g_res);
    cudaGetSymbolAddress((void**)&qkv,  g_qkv);
    cudaGetSymbolAddress((void**)&kc,   g_kc);
    cudaGetSymbolAddress((void**)&vc,   g_vc);
    cudaGetSymbolAddress((void**)&hn,   g_hn);
    cudaGetSymbolAddress((void**)&at,   g_at);
    cudaGetSymbolAddress((void**)&ac,   g_ac);
    cudaGetSymbolAddress((void**)&wh,   g_wh);
    cudaGetSymbolAddress((void**)&wl,   g_wl);

    int flash_smem = (int)sizeof(FlashSmem);
    cudaFuncSetAttribute(flash_kernel, cudaFuncAttributeMaxDynamicSharedMemorySize, flash_smem);
    cudaFuncSetAttribute(gemm_f16, cudaFuncAttributeMaxDynamicSharedMemorySize, GEMM_SMEM);

    // fused one-shot weight prep (transpose + x64 scale + fp16 2-term split,
    // gate/up columns interleaved)
    prep_weights<<<2 * TILES_PER_LAYER, dim3(32, 8)>>>(
        w_qkv, w_o, w_gate_up, w_down, wh, wl);

    embed_kernel<<<Tc, 256>>>(input_ids, embed, res);

    for (int l = 0; l < Lc; l++) {
        __half* whl = wh + (size_t)l * WT_PER_L;
        __half* wll = wl + (size_t)l * WT_PER_L;

        // ln1 (res is the complete residual at this point)
        addnorm_kernel<<<Tc, 256>>>(res, ln1_w + (size_t)l * Hc, nullptr, hn);

        gemm_f16<<<dim3(Tc / 128, QKVN / 128), 256, GEMM_SMEM>>>(
            hn, whl + WT_QKV_OFF, wll + WT_QKV_OFF, qkv, nullptr, nullptr,
            Tc, QKVN, Hc);

        rope_kernel<<<Tc, 128>>>(qkv, positions, kc, vc);

        flash_kernel<<<dim3(Sc / 64, NHc, Bc), 256, flash_smem>>>(qkv, kc, vc, at);

        // o-proj fused with residual add (res += attn_out)
        gemm_f16<<<dim3(Tc / 128, Hc / 128), 256, GEMM_SMEM>>>(
            at, whl + WT_O_OFF, wll + WT_O_OFF, res, res, nullptr,
            Tc, Hc, Hc);

        // ln2
        addnorm_kernel<<<Tc, 256>>>(res, ln2_w + (size_t)l * Hc, nullptr, hn);

        // gate_up GEMM with fused SwiGLU epilogue -> ac (fp16)
        gemm_f16<<<dim3(Tc / 128, GUN / 128), 256, GEMM_SMEM>>>(
            hn, whl + WT_GU_OFF, wll + WT_GU_OFF, nullptr, nullptr, ac,
            Tc, GUN, Hc);

        // down-proj fused with residual add (res += mlp_out)
        gemm_f16<<<dim3(Tc / 128, Hc / 128), 256, GEMM_SMEM>>>(
            ac, whl + WT_DN_OFF, wll + WT_DN_OFF, res, res, nullptr,
            Tc, Hc, Ic);
    }

    addnorm_kernel<<<Tc, 256>>>(res, norm_w, out, nullptr);
}

// round 10
// speedup vs baseline: 1.8045x; 1.1871x over previous
#include <cuda_runtime.h>
#include <cuda_fp16.h>
#include <math.h>
#include <stdint.h>

// ---------------------------------------------------------------------------
// Model constants
// ---------------------------------------------------------------------------
#define Lc 2
#define Hc 2048
#define NHc 32
#define NKVc 4
#define HDc 64
#define Ic 5632
#define Bc 2
#define Sc 1024
#define Tc (Bc * Sc)                   // 2048 tokens
#define QKVN ((NHc + 2 * NKVc) * HDc)  // 2560
#define GUN (2 * Ic)                   // 11264
#define EPSc 1e-5f
#define WSCALE 64.0f
#define WINV   0.015625f               // 1/64

// ---------------------------------------------------------------------------
// Scratch (static device globals; no allocation allowed)
// ---------------------------------------------------------------------------
__device__ float g_res [Tc * Hc];
__device__ float g_qkv [Tc * QKVN];

// fp16 activations (GEMM A operands)
__device__ __half g_hn [Tc * Hc];
__device__ __half g_at [Tc * Hc];
__device__ __half g_ac [(size_t)Tc * Ic];

// split fp16 Q (pre-scaled by 0.125) and KV caches
__device__ __half g_qh [Tc * Hc];
__device__ __half g_ql [Tc * Hc];
__device__ __half g_kh [Bc * NKVc * Sc * HDc];
__device__ __half g_kl [Bc * NKVc * Sc * HDc];
__device__ __half g_vh [Bc * NKVc * Sc * HDc];
__device__ __half g_vl [Bc * NKVc * Sc * HDc];

// Transposed split weights (x64 scaled, fp16 hi+lo exact 2-term):
// per layer [qkv_t(QKVN,H) | o_t(H,H) | gu_t(GUN,H, gate/up interleaved) | down_t(H,I)]
#define WT_QKV_OFF 0
#define WT_O_OFF   ((size_t)QKVN * Hc)
#define WT_GU_OFF  (WT_O_OFF + (size_t)Hc * Hc)
#define WT_DN_OFF  (WT_GU_OFF + (size_t)GUN * Hc)
#define WT_PER_L   (WT_DN_OFF + (size_t)Hc * Ic)
__device__ __half g_wh[2 * WT_PER_L];
__device__ __half g_wl[2 * WT_PER_L];

// ---------------------------------------------------------------------------
// Helpers
// ---------------------------------------------------------------------------
__device__ __forceinline__ uint32_t smem_u32(const void* p) {
    uint32_t a;
    asm("{ .reg .u64 t; cvta.to.shared.u64 t, %1; cvt.u32.u64 %0, t; }"
        : "=r"(a) : "l"(p));
    return a;
}

__device__ __forceinline__ void cp_async16(uint32_t smem_addr, const void* gptr) {
    asm volatile("cp.async.cg.shared.global [%0], [%1], 16;"
                 :: "r"(smem_addr), "l"(gptr) : "memory");
}
#define CP_COMMIT() asm volatile("cp.async.commit_group;" ::: "memory")
#define CP_WAIT0()  asm volatile("cp.async.wait_group 0;" ::: "memory")
#define CP_WAIT2()  asm volatile("cp.async.wait_group 2;" ::: "memory")

__device__ __forceinline__ void mma_f16(float* d, const uint32_t* a, const uint32_t* b) {
    asm volatile(
        "mma.sync.aligned.m16n8k16.row.col.f32.f16.f16.f32 "
        "{%0,%1,%2,%3}, {%4,%5,%6,%7}, {%8,%9}, {%0,%1,%2,%3};"
        : "+f"(d[0]), "+f"(d[1]), "+f"(d[2]), "+f"(d[3])
        : "r"(a[0]), "r"(a[1]), "r"(a[2]), "r"(a[3]),
          "r"(b[0]), "r"(b[1]));
}

#define LDSM4(R, A) \
    asm volatile("ldmatrix.sync.aligned.m8n8.x4.shared.b16 {%0,%1,%2,%3}, [%4];" \
        : "=r"((R)[0]), "=r"((R)[1]), "=r"((R)[2]), "=r"((R)[3]) : "r"(A))

#define LDSM4T(R, A) \
    asm volatile("ldmatrix.sync.aligned.m8n8.x4.trans.shared.b16 {%0,%1,%2,%3}, [%4];" \
        : "=r"((R)[0]), "=r"((R)[1]), "=r"((R)[2]), "=r"((R)[3]) : "r"(A))

__device__ __forceinline__ void split2h(float x, __half& hi, __half& lo) {
    hi = __float2half_rn(x);
    lo = __float2half_rn(x - __half2float(hi));
}

__device__ __forceinline__ uint32_t packh2(float a, float b) {
    __half2 h = __floats2half2_rn(a, b);
    return *(uint32_t*)&h;
}

// ---------------------------------------------------------------------------
// Fused weight prep: transpose + x64 scale + exact fp16 2-term split.
// gate_up destination rows interleaved (gate i -> 2i, up i -> 2i+1).
// ---------------------------------------------------------------------------
#define TILES_PER_LAYER 43008
__global__ void prep_weights(const float* __restrict__ wqkv,
                             const float* __restrict__ wo,
                             const float* __restrict__ wgu,
                             const float* __restrict__ wdn,
                             __half* __restrict__ wth,
                             __half* __restrict__ wtl) {
    __shared__ float tile[32][33];
    int bid = blockIdx.x;
    int l = 0;
    if (bid >= TILES_PER_LAYER) { l = 1; bid -= TILES_PER_LAYER; }
    size_t loff = (size_t)l * WT_PER_L;

    const float* src;
    __half *hi, *lo;
    int K, N;
    int gu_mode = 0;
    if (bid < 5120) {
        src = wqkv + (size_t)l * Hc * QKVN;
        hi = wth + loff + WT_QKV_OFF; lo = wtl + loff + WT_QKV_OFF;
        K = Hc; N = QKVN;
    } else if (bid < 9216) {
        bid -= 5120;
        src = wo + (size_t)l * Hc * Hc;
        hi = wth + loff + WT_O_OFF; lo = wtl + loff + WT_O_OFF;
        K = Hc; N = Hc;
    } else if (bid < 31744) {
        bid -= 9216;
        src = wgu + (size_t)l * Hc * GUN;
        hi = wth + loff + WT_GU_OFF; lo = wtl + loff + WT_GU_OFF;
        K = Hc; N = GUN;
        gu_mode = 1;
    } else {
        bid -= 31744;
        src = wdn + (size_t)l * Ic * Hc;
        hi = wth + loff + WT_DN_OFF; lo = wtl + loff + WT_DN_OFF;
        K = Ic; N = Hc;
    }
    int tilesX = N / 32;
    int nb = (bid % tilesX) * 32;
    int kb = (bid / tilesX) * 32;

#pragma unroll
    for (int i = threadIdx.y; i < 32; i += 8)
        tile[i][threadIdx.x] = src[(size_t)(kb + i) * N + nb + threadIdx.x];
    __syncthreads();
#pragma unroll
    for (int i = threadIdx.y; i < 32; i += 8) {
        float v = tile[threadIdx.x][i] * WSCALE;
        __half h, lv;
        split2h(v, h, lv);
        int col = nb + i;
        if (gu_mode) col = (col < Ic) ? (2 * col) : (2 * (col - Ic) + 1);
        size_t idx = (size_t)col * K + kb + threadIdx.x;
        hi[idx] = h;
        lo[idx] = lv;
    }
}

// ---------------------------------------------------------------------------
// fp16 2-term GEMM (unchanged from R9)
// ---------------------------------------------------------------------------
#define RPITCH 48
#define ARRB   (128 * RPITCH)
#define STAGEB (3 * ARRB)
#define GEMM_SMEM (4 * STAGEB)

__global__ void __launch_bounds__(256, 2)
gemm_f16(const __half* __restrict__ A,
         const __half* __restrict__ Wh,
         const __half* __restrict__ Wl,
         float* __restrict__ C, const float* __restrict__ addend,
         __half* __restrict__ actout,
         int M, int N, int K) {
    extern __shared__ char smraw[];
    uint32_t sbase = smem_u32(smraw);

    const int tid  = threadIdx.x;
    const int warp = tid >> 5;
    const int lane = tid & 31;
    const int wm   = (warp >> 1) * 32;
    const int wn   = (warp & 1) * 64;
    const int grp  = lane >> 2;
    const int tig  = lane & 3;

    const int m0 = blockIdx.x * 128;
    const int n0 = blockIdx.y * 128;

    const int li = lane >> 3;
    const int lr = lane & 7;
    const uint32_t aoffl = (uint32_t)(((li & 1) * 8 + lr) * RPITCH + (li >> 1) * 16);
    const uint32_t boffl = (uint32_t)(((li >> 1) * 8 + lr) * RPITCH + (li & 1) * 16);

    const int r0   = tid >> 1;
    const int half = tid & 1;
    const uint32_t sdst = (uint32_t)(r0 * RPITCH + half * 16);
    const __half* pA  = A  + (size_t)(m0 + r0) * K + half * 8;
    const __half* pWh = Wh + (size_t)(n0 + r0) * K + half * 8;
    const __half* pWl = Wl + (size_t)(n0 + r0) * K + half * 8;

    const int nkt = K >> 4;

    float c[2][8][4];
#pragma unroll
    for (int mt = 0; mt < 2; mt++)
#pragma unroll
        for (int nt = 0; nt < 8; nt++)
#pragma unroll
            for (int i = 0; i < 4; i++) c[mt][nt][i] = 0.f;

#pragma unroll
    for (int s = 0; s < 3; s++) {
        uint32_t b = sbase + (uint32_t)s * STAGEB + sdst;
        int ko = s * 16;
        cp_async16(b,            pA  + ko);
        cp_async16(b + ARRB,     pWh + ko);
        cp_async16(b + 2 * ARRB, pWl + ko);
        CP_COMMIT();
    }

    for (int kt = 0; kt < nkt; kt++) {
        CP_WAIT2();
        __syncthreads();

        uint32_t sb = sbase + (uint32_t)(kt & 3) * STAGEB;

        uint32_t a[2][4];
#pragma unroll
        for (int mt = 0; mt < 2; mt++) {
            uint32_t aaddr = sb + (uint32_t)((wm + mt * 16) * RPITCH) + aoffl;
            LDSM4(a[mt], aaddr);
        }
#pragma unroll
        for (int nh = 0; nh < 2; nh++) {
            uint32_t wh[2][4], wl[2][4];
#pragma unroll
            for (int pq = 0; pq < 2; pq++) {
                uint32_t baddr = sb + ARRB +
                                 (uint32_t)((wn + nh * 32 + pq * 16) * RPITCH) + boffl;
                LDSM4(wh[pq], baddr);
                LDSM4(wl[pq], baddr + ARRB);
            }
#pragma unroll
            for (int mt = 0; mt < 2; mt++)
#pragma unroll
                for (int pq = 0; pq < 2; pq++)
#pragma unroll
                    for (int h = 0; h < 2; h++)
                        mma_f16(c[mt][nh * 4 + pq * 2 + h], a[mt], &wh[pq][h * 2]);
#pragma unroll
            for (int mt = 0; mt < 2; mt++)
#pragma unroll
                for (int pq = 0; pq < 2; pq++)
#pragma unroll
                    for (int h = 0; h < 2; h++)
                        mma_f16(c[mt][nh * 4 + pq * 2 + h], a[mt], &wl[pq][h * 2]);
        }

        if (kt + 3 < nkt) {
            uint32_t b = sbase + (uint32_t)((kt + 3) & 3) * STAGEB + sdst;
            int ko = (kt + 3) * 16;
            cp_async16(b,            pA  + ko);
            cp_async16(b + ARRB,     pWh + ko);
            cp_async16(b + 2 * ARRB, pWl + ko);
        }
        CP_COMMIT();
    }

    if (actout) {
#pragma unroll
        for (int mt = 0; mt < 2; mt++) {
            int row = m0 + wm + mt * 16 + grp;
#pragma unroll
            for (int nt = 0; nt < 8; nt++) {
                int col = n0 + wn + nt * 8 + tig * 2;
                int pair = col >> 1;
                {
                    float g = c[mt][nt][0] * WINV;
                    float u = c[mt][nt][1] * WINV;
                    float sig = 1.0f / (1.0f + __expf(-g));
                    actout[(size_t)row * Ic + pair] = __float2half_rn(g * sig * u);
                }
                {
                    float g = c[mt][nt][2] * WINV;
                    float u = c[mt][nt][3] * WINV;
                    float sig = 1.0f / (1.0f + __expf(-g));
                    actout[(size_t)(row + 8) * Ic + pair] = __float2half_rn(g * sig * u);
                }
            }
        }
    } else {
#pragma unroll
        for (int mt = 0; mt < 2; mt++) {
            int row = m0 + wm + mt * 16 + grp;
#pragma unroll
            for (int nt = 0; nt < 8; nt++) {
                int col = n0 + wn + nt * 8 + tig * 2;
                size_t i0 = (size_t)row * N + col;
                size_t i1 = (size_t)(row + 8) * N + col;
                float2 v0 = make_float2(c[mt][nt][0] * WINV, c[mt][nt][1] * WINV);
                float2 v1 = make_float2(c[mt][nt][2] * WINV, c[mt][nt][3] * WINV);
                if (addend) {
                    float2 a0 = *(const float2*)(addend + i0);
                    float2 a1 = *(const float2*)(addend + i1);
                    v0.x += a0.x; v0.y += a0.y;
                    v1.x += a1.x; v1.y += a1.y;
                }
                *(float2*)(C + i0) = v0;
                *(float2*)(C + i1) = v1;
            }
        }
    }
}

// ---------------------------------------------------------------------------
// Embedding gather
// ---------------------------------------------------------------------------
__global__ void embed_kernel(const int* __restrict__ ids,
                             const float* __restrict__ embed,
                             float* __restrict__ res) {
    int t = blockIdx.x;
    int id = ids[t];
    const float4* src = (const float4*)(embed + (size_t)id * Hc);
    float4* dst = (float4*)(res + (size_t)t * Hc);
    for (int i = threadIdx.x; i < Hc / 4; i += blockDim.x)
        dst[i] = src[i];
}

// ---------------------------------------------------------------------------
// RMSNorm. Output fp32 and/or fp16.
// ---------------------------------------------------------------------------
__global__ void addnorm_kernel(const float* __restrict__ res,
                               const float* __restrict__ w,
                               float* __restrict__ outf,
                               __half* __restrict__ oh) {
    int t = blockIdx.x;
    int tid = threadIdx.x;
    const float* rp = res + (size_t)t * Hc;
    float vals[8];
    float ss = 0.f;
#pragma unroll
    for (int i = 0; i < 8; i++) {
        int idx = tid + i * 256;
        float v = rp[idx];
        vals[i] = v;
        ss += v * v;
    }
    __shared__ float warp_s[8];
#pragma unroll
    for (int off = 16; off > 0; off >>= 1)
        ss += __shfl_down_sync(0xffffffff, ss, off);
    if ((tid & 31) == 0) warp_s[tid >> 5] = ss;
    __syncthreads();
    if (tid < 8) {
        float v = warp_s[tid];
#pragma unroll
        for (int off = 4; off > 0; off >>= 1)
            v += __shfl_down_sync(0xff, v, off);
        if (tid == 0) warp_s[0] = v;
    }
    __syncthreads();
    float inv = rsqrtf(warp_s[0] * (1.0f / Hc) + EPSc);
#pragma unroll
    for (int i = 0; i < 8; i++) {
        int idx = tid + i * 256;
        float o = vals[i] * inv * w[idx];
        if (outf) outf[(size_t)t * Hc + idx] = o;
        if (oh)   oh[(size_t)t * Hc + idx] = __float2half_rn(o);
    }
}

// ---------------------------------------------------------------------------
// RoPE + split-fp16 scatter: Q (pre-scaled 0.125, exact split), K cache, V cache
// ---------------------------------------------------------------------------
__global__ void rope_kernel(const float* __restrict__ qkv,
                            const int* __restrict__ pos,
                            __half* __restrict__ qh, __half* __restrict__ ql,
                            __half* __restrict__ kh, __half* __restrict__ kl,
                            __half* __restrict__ vh, __half* __restrict__ vl) {
    int t = blockIdx.x;
    int b = t / Sc, s = t % Sc;
    int tid = threadIdx.x;
    float p = (float)pos[s];
    const float lt = logf(10000.f) / 32.f;

    for (int w = tid; w < (NHc + NKVc) * 32; w += blockDim.x) {
        int head = w / 32, j = w % 32;
        float ang = p * __expf(-(float)j * lt);
        float c = cosf(ang), sn = sinf(ang);
        if (head < NHc) {
            const float* base = qkv + (size_t)t * QKVN + head * HDc;
            float x1 = base[j], x2 = base[j + 32];
            float r1 = (x1 * c - x2 * sn) * 0.125f;
            float r2 = (x2 * c + x1 * sn) * 0.125f;
            size_t o = (size_t)t * Hc + head * HDc;
            __half h1, l1, h2, l2;
            split2h(r1, h1, l1);
            split2h(r2, h2, l2);
            qh[o + j] = h1;  ql[o + j] = l1;
            qh[o + j + 32] = h2;  ql[o + j + 32] = l2;
        } else {
            int hk = head - NHc;
            const float* base = qkv + (size_t)t * QKVN + NHc * HDc + hk * HDc;
            float x1 = base[j], x2 = base[j + 32];
            float r1 = x1 * c - x2 * sn;
            float r2 = x2 * c + x1 * sn;
            size_t o = (((size_t)(b * NKVc + hk)) * Sc + s) * HDc;
            __half h1, l1, h2, l2;
            split2h(r1, h1, l1);
            split2h(r2, h2, l2);
            kh[o + j] = h1;  kl[o + j] = l1;
            kh[o + j + 32] = h2;  kl[o + j + 32] = l2;
        }
    }
    for (int w = tid; w < NKVc * HDc; w += blockDim.x) {
        int hv = w / HDc, d = w % HDc;
        float v = qkv[(size_t)t * QKVN + (NHc + NKVc) * HDc + hv * HDc + d];
        size_t o = (((size_t)(b * NKVc + hv)) * Sc + s) * HDc + d;
        __half h1, l1;
        split2h(v, h1, l1);
        vh[o] = h1;  vl[o] = l1;
    }
}

// ---------------------------------------------------------------------------
// Flash attention on fp16 MMA. One block = 64 queries of one (b, head).
// 4 warps x 16 rows. QK: 3-term split (exact). PV: P fp16 x V 2-term split.
// K/V tiles double-buffered via cp.async. Scores/softmax/P all in registers.
// ---------------------------------------------------------------------------
#define FPITCHB 144                 // bytes per 64-half row (128 + 16 pad)
#define FARR    (64 * FPITCHB)      // 9216 per array
#define FBUF    (4 * FARR)          // 36864 per buffer (Kh, Kl, Vh, Vl)
#define FLASH_SMEM (2 * FBUF)       // 73728

__global__ void __launch_bounds__(128)
flash_mma(const __half* __restrict__ qhg, const __half* __restrict__ qlg,
          const __half* __restrict__ khg, const __half* __restrict__ klg,
          const __half* __restrict__ vhg, const __half* __restrict__ vlg,
          __half* __restrict__ aout) {
    extern __shared__ char smraw[];
    uint32_t sbase = smem_u32(smraw);

    const int qb = blockIdx.x;
    const int h  = blockIdx.y;
    const int b  = blockIdx.z;
    const int hkv = h / (NHc / NKVc);
    const int tid = threadIdx.x;
    const int w   = tid >> 5;
    const int lane = tid & 31;
    const int grp = lane >> 2;
    const int tig = lane & 3;
    const int li = lane >> 3;
    const int lr = lane & 7;
    // K (B operand, K-major [key][d]): non-trans pattern
    const uint32_t boffl = (uint32_t)(((li >> 1) * 8 + lr) * FPITCHB + (li & 1) * 16);
    // V (B operand via trans, [key][d]): trans pattern
    const uint32_t voffl = (uint32_t)(((li & 1) * 8 + lr) * FPITCHB + (li >> 1) * 16);

    // ---- Q fragments in registers (loaded once) ----
    uint32_t qfh[4][4], qfl[4][4];
    {
        int row0 = b * Sc + qb * 64 + w * 16 + grp;
#pragma unroll
        for (int kt = 0; kt < 4; kt++) {
#pragma unroll
            for (int i = 0; i < 4; i++) {
                int row = row0 + (i & 1) * 8;
                int col = h * HDc + kt * 16 + (i >> 1) * 8 + tig * 2;
                qfh[kt][i] = *(const uint32_t*)&qhg[(size_t)row * Hc + col];
                qfl[kt][i] = *(const uint32_t*)&qlg[(size_t)row * Hc + col];
            }
        }
    }

    float o[8][4];
#pragma unroll
    for (int dn = 0; dn < 8; dn++)
#pragma unroll
        for (int i = 0; i < 4; i++) o[dn][i] = 0.f;
    float m0 = -1e30f, m1 = -1e30f, l0 = 0.f, l1 = 0.f;

    // staging: per array 512 chunks of 16B; thread handles 4 per array
    const size_t kvbase = ((size_t)(b * NKVc + hkv)) * Sc;

    // prologue: load kb=0 into buffer 0
    {
        uint32_t bb = sbase;
#pragma unroll
        for (int i = 0; i < 4; i++) {
            int chunk = tid + i * 128;
            int r = chunk >> 3, cc = chunk & 7;
            uint32_t so = (uint32_t)(r * FPITCHB + cc * 16);
            size_t go = (kvbase + r) * HDc + cc * 8;
            cp_async16(bb + so,            khg + go);
            cp_async16(bb + FARR + so,     klg + go);
            cp_async16(bb + 2 * FARR + so, vhg + go);
            cp_async16(bb + 3 * FARR + so, vlg + go);
        }
        CP_COMMIT();
    }

    for (int kb = 0; kb <= qb; kb++) {
        CP_WAIT0();
        __syncthreads();

        // prefetch kb+1 into other buffer (overlaps compute)
        if (kb + 1 <= qb) {
            uint32_t bb = sbase + (uint32_t)((kb + 1) & 1) * FBUF;
#pragma unroll
            for (int i = 0; i < 4; i++) {
                int chunk = tid + i * 128;
                int r = chunk >> 3, cc = chunk & 7;
                uint32_t so = (uint32_t)(r * FPITCHB + cc * 16);
                size_t go = (kvbase + (kb + 1) * 64 + r) * HDc + cc * 8;
                cp_async16(bb + so,            khg + go);
                cp_async16(bb + FARR + so,     klg + go);
                cp_async16(bb + 2 * FARR + so, vhg + go);
                cp_async16(bb + 3 * FARR + so, vlg + go);
            }
            CP_COMMIT();
        }

        uint32_t sb = sbase + (uint32_t)(kb & 1) * FBUF;

        // ---- QK: S = Q . K^T (3-term split) ----
        float s[8][4];
#pragma unroll
        for (int nt = 0; nt < 8; nt++)
#pragma unroll
            for (int i = 0; i < 4; i++) s[nt][i] = 0.f;

#pragma unroll
        for (int kt = 0; kt < 4; kt++) {
            uint32_t kfh[4][4], kfl[4][4];
#pragma unroll
            for (int kg = 0; kg < 4; kg++) {
                uint32_t addr = sb + (uint32_t)(kg * 16 * FPITCHB) + (uint32_t)(kt * 32) + boffl;
                LDSM4(kfh[kg], addr);
                LDSM4(kfl[kg], addr + FARR);
            }
#pragma unroll
            for (int kg = 0; kg < 4; kg++)
#pragma unroll
                for (int hh = 0; hh < 2; hh++)
                    mma_f16(s[kg * 2 + hh], qfh[kt], &kfh[kg][hh * 2]);
#pragma unroll
            for (int kg = 0; kg < 4; kg++)
#pragma unroll
                for (int hh = 0; hh < 2; hh++)
                    mma_f16(s[kg * 2 + hh], qfh[kt], &kfl[kg][hh * 2]);
#pragma unroll
            for (int kg = 0; kg < 4; kg++)
#pragma unroll
                for (int hh = 0; hh < 2; hh++)
                    mma_f16(s[kg * 2 + hh], qfl[kt], &kfh[kg][hh * 2]);
        }

        // ---- causal mask on diagonal tile ----
        if (kb == qb) {
            int rl0 = w * 16 + grp;
            int rl1 = rl0 + 8;
#pragma unroll
            for (int nt = 0; nt < 8; nt++) {
                int cl = nt * 8 + tig * 2;
                if (cl     > rl0) s[nt][0] = -1e30f;
                if (cl + 1 > rl0) s[nt][1] = -1e30f;
                if (cl     > rl1) s[nt][2] = -1e30f;
                if (cl + 1 > rl1) s[nt][3] = -1e30f;
            }
        }

        // ---- online softmax (rows grp, grp+8; stats replicated over quad) ----
        {
            float mx0 = -1e30f, mx1 = -1e30f;
#pragma unroll
            for (int nt = 0; nt < 8; nt++) {
                mx0 = fmaxf(mx0, fmaxf(s[nt][0], s[nt][1]));
                mx1 = fmaxf(mx1, fmaxf(s[nt][2], s[nt][3]));
            }
            mx0 = fmaxf(mx0, __shfl_xor_sync(0xffffffffu, mx0, 1));
            mx0 = fmaxf(mx0, __shfl_xor_sync(0xffffffffu, mx0, 2));
            mx1 = fmaxf(mx1, __shfl_xor_sync(0xffffffffu, mx1, 1));
            mx1 = fmaxf(mx1, __shfl_xor_sync(0xffffffffu, mx1, 2));
            float mn0 = fmaxf(m0, mx0);
            float mn1 = fmaxf(m1, mx1);
            float a0 = __expf(m0 - mn0);
            float a1 = __expf(m1 - mn1);
            float su0 = 0.f, su1 = 0.f;
#pragma unroll
            for (int nt = 0; nt < 8; nt++) {
                s[nt][0] = __expf(s[nt][0] - mn0); su0 += s[nt][0];
                s[nt][1] = __expf(s[nt][1] - mn0); su0 += s[nt][1];
                s[nt][2] = __expf(s[nt][2] - mn1); su1 += s[nt][2];
                s[nt][3] = __expf(s[nt][3] - mn1); su1 += s[nt][3];
            }
            su0 += __shfl_xor_sync(0xffffffffu, su0, 1);
            su0 += __shfl_xor_sync(0xffffffffu, su0, 2);
            su1 += __shfl_xor_sync(0xffffffffu, su1, 1);
            su1 += __shfl_xor_sync(0xffffffffu, su1, 2);
            l0 = l0 * a0 + su0;
            l1 = l1 * a1 + su1;
            m0 = mn0;
            m1 = mn1;
#pragma unroll
            for (int dn = 0; dn < 8; dn++) {
                o[dn][0] *= a0; o[dn][1] *= a0;
                o[dn][2] *= a1; o[dn][3] *= a1;
            }
        }

        // ---- PV: O += P . V (P fp16, V 2-term split) ----
#pragma unroll
        for (int kt = 0; kt < 4; kt++) {
            uint32_t a[4];
            a[0] = packh2(s[2 * kt][0],     s[2 * kt][1]);
            a[1] = packh2(s[2 * kt][2],     s[2 * kt][3]);
            a[2] = packh2(s[2 * kt + 1][0], s[2 * kt + 1][1]);
            a[3] = packh2(s[2 * kt + 1][2], s[2 * kt + 1][3]);
            uint32_t vfh[4][4], vfl[4][4];
#pragma unroll
            for (int db = 0; db < 4; db++) {
                uint32_t addr = sb + 2 * FARR + (uint32_t)(kt * 16 * FPITCHB) + (uint32_t)(db * 32) + voffl;
                LDSM4T(vfh[db], addr);
                LDSM4T(vfl[db], addr + FARR);
            }
#pragma unroll
            for (int db = 0; db < 4; db++)
#pragma unroll
                for (int hh = 0; hh < 2; hh++)
                    mma_f16(o[db * 2 + hh], a, &vfh[db][hh * 2]);
#pragma unroll
            for (int db = 0; db < 4; db++)
#pragma unroll
                for (int hh = 0; hh < 2; hh++)
                    mma_f16(o[db * 2 + hh], a, &vfl[db][hh * 2]);
        }
    }

    // ---- epilogue ----
    {
        float i0 = 1.0f / l0;
        float i1 = 1.0f / l1;
        size_t row0 = (size_t)(b * Sc + qb * 64 + w * 16 + grp);
#pragma unroll
        for (int dn = 0; dn < 8; dn++) {
            int col = h * HDc + dn * 8 + tig * 2;
            __half2 p0 = __floats2half2_rn(o[dn][0] * i0, o[dn][1] * i0);
            __half2 p1 = __floats2half2_rn(o[dn][2] * i1, o[dn][3] * i1);
            *(__half2*)&aout[row0 * Hc + col] = p0;
            *(__half2*)&aout[(row0 + 8) * Hc + col] = p1;
        }
    }
}

// ---------------------------------------------------------------------------
// Launch
// ---------------------------------------------------------------------------
extern "C" void kernel_launch(void* const* d_in, const int* in_sizes, int n_in,
                              void* d_out, int out_size) {
    const int*   input_ids = (const int*)d_in[0];
    const int*   positions = (const int*)d_in[1];
    const float* embed     = (const float*)d_in[2];
    const float* w_qkv     = (const float*)d_in[3];
    const float* w_o       = (const float*)d_in[4];
    const float* w_gate_up = (const float*)d_in[5];
    const float* w_down    = (const float*)d_in[6];
    const float* ln1_w     = (const float*)d_in[7];
    const float* ln2_w     = (const float*)d_in[8];
    const float* norm_w    = (const float*)d_in[9];
    float* out = (float*)d_out;

    float *res, *qkv;
    __half *hn, *at, *ac, *wh, *wl, *qh, *ql, *kh, *kl, *vh, *vl;
    cudaGetSymbolAddress((void**)&res,  g_res);
    cudaGetSymbolAddress((void**)&qkv,  g_qkv);
    cudaGetSymbolAddress((void**)&hn,   g_hn);
    cudaGetSymbolAddress((void**)&at,   g_at);
    cudaGetSymbolAddress((void**)&ac,   g_ac);
    cudaGetSymbolAddress((void**)&wh,   g_wh);
    cudaGetSymbolAddress((void**)&wl,   g_wl);
    cudaGetSymbolAddress((void**)&qh,   g_qh);
    cudaGetSymbolAddress((void**)&ql,   g_ql);
    cudaGetSymbolAddress((void**)&kh,   g_kh);
    cudaGetSymbolAddress((void**)&kl,   g_kl);
    cudaGetSymbolAddress((void**)&vh,   g_vh);
    cudaGetSymbolAddress((void**)&vl,   g_vl);

    cudaFuncSetAttribute(flash_mma, cudaFuncAttributeMaxDynamicSharedMemorySize, FLASH_SMEM);
    cudaFuncSetAttribute(gemm_f16, cudaFuncAttributeMaxDynamicSharedMemorySize, GEMM_SMEM);

    prep_weights<<<2 * TILES_PER_LAYER, dim3(32, 8)>>>(
        w_qkv, w_o, w_gate_up, w_down, wh, wl);

    embed_kernel<<<Tc, 256>>>(input_ids, embed, res);

    for (int l = 0; l < Lc; l++) {
        __half* whl = wh + (size_t)l * WT_PER_L;
        __half* wll = wl + (size_t)l * WT_PER_L;

        addnorm_kernel<<<Tc, 256>>>(res, ln1_w + (size_t)l * Hc, nullptr, hn);

        gemm_f16<<<dim3(Tc / 128, QKVN / 128), 256, GEMM_SMEM>>>(
            hn, whl + WT_QKV_OFF, wll + WT_QKV_OFF, qkv, nullptr, nullptr,
            Tc, QKVN, Hc);

        rope_kernel<<<Tc, 128>>>(qkv, positions, qh, ql, kh, kl, vh, vl);

        flash_mma<<<dim3(Sc / 64, NHc, Bc), 128, FLASH_SMEM>>>(
            qh, ql, kh, kl, vh, vl, at);

        gemm_f16<<<dim3(Tc / 128, Hc / 128), 256, GEMM_SMEM>>>(
            at, whl + WT_O_OFF, wll + WT_O_OFF, res, res, nullptr,
            Tc, Hc, Hc);

        addnorm_kernel<<<Tc, 256>>>(res, ln2_w + (size_t)l * Hc, nullptr, hn);

        gemm_f16<<<dim3(Tc / 128, GUN / 128), 256, GEMM_SMEM>>>(
            hn, whl + WT_GU_OFF, wll + WT_GU_OFF, nullptr, nullptr, ac,
            Tc, GUN, Hc);

        gemm_f16<<<dim3(Tc / 128, Hc / 128), 256, GEMM_SMEM>>>(
            ac, whl + WT_DN_OFF, wll + WT_DN_OFF, res, res, nullptr,
            Tc, Hc, Ic);
    }

    addnorm_kernel<<<Tc, 256>>>(res, norm_w, out, nullptr);
}

// round 11
// speedup vs baseline: 2.1324x; 1.1817x over previous
#include <cuda_runtime.h>
#include <cuda_fp16.h>
#include <math.h>
#include <stdint.h>

// ---------------------------------------------------------------------------
// Model constants
// ---------------------------------------------------------------------------
#define Lc 2
#define Hc 2048
#define NHc 32
#define NKVc 4
#define HDc 64
#define Ic 5632
#define Bc 2
#define Sc 1024
#define Tc (Bc * Sc)                   // 2048 tokens
#define QKVN ((NHc + 2 * NKVc) * HDc)  // 2560
#define GUN (2 * Ic)                   // 11264
#define EPSc 1e-5f
#define WSCALE 64.0f
#define WINV   0.015625f               // 1/64

// ---------------------------------------------------------------------------
// Scratch (static device globals; no allocation allowed)
// ---------------------------------------------------------------------------
__device__ float g_res [Tc * Hc];
__device__ float g_qkv [Tc * QKVN];

// fp16 activations (GEMM A operands)
__device__ __half g_hn [Tc * Hc];
__device__ __half g_at [Tc * Hc];
__device__ __half g_ac [(size_t)Tc * Ic];

// split fp16 Q (pre-scaled by 0.125) and KV caches
__device__ __half g_qh [Tc * Hc];
__device__ __half g_ql [Tc * Hc];
__device__ __half g_kh [Bc * NKVc * Sc * HDc];
__device__ __half g_kl [Bc * NKVc * Sc * HDc];
__device__ __half g_vh [Bc * NKVc * Sc * HDc];
__device__ __half g_vl [Bc * NKVc * Sc * HDc];

// Transposed split weights (x64 scaled, fp16 hi+lo exact 2-term):
// per layer [qkv_t(QKVN,H) | o_t(H,H) | gu_t(GUN,H, gate/up interleaved) | down_t(H,I)]
#define WT_QKV_OFF 0
#define WT_O_OFF   ((size_t)QKVN * Hc)
#define WT_GU_OFF  (WT_O_OFF + (size_t)Hc * Hc)
#define WT_DN_OFF  (WT_GU_OFF + (size_t)GUN * Hc)
#define WT_PER_L   (WT_DN_OFF + (size_t)Hc * Ic)
__device__ __half g_wh[2 * WT_PER_L];
__device__ __half g_wl[2 * WT_PER_L];

// ---------------------------------------------------------------------------
// Helpers
// ---------------------------------------------------------------------------
__device__ __forceinline__ uint32_t smem_u32(const void* p) {
    uint32_t a;
    asm("{ .reg .u64 t; cvta.to.shared.u64 t, %1; cvt.u32.u64 %0, t; }"
        : "=r"(a) : "l"(p));
    return a;
}

__device__ __forceinline__ void cp_async16(uint32_t smem_addr, const void* gptr) {
    asm volatile("cp.async.cg.shared.global [%0], [%1], 16;"
                 :: "r"(smem_addr), "l"(gptr) : "memory");
}
#define CP_COMMIT() asm volatile("cp.async.commit_group;" ::: "memory")
#define CP_WAIT0()  asm volatile("cp.async.wait_group 0;" ::: "memory")
#define CP_WAIT2()  asm volatile("cp.async.wait_group 2;" ::: "memory")

__device__ __forceinline__ void mma_f16(float* d, const uint32_t* a, const uint32_t* b) {
    asm volatile(
        "mma.sync.aligned.m16n8k16.row.col.f32.f16.f16.f32 "
        "{%0,%1,%2,%3}, {%4,%5,%6,%7}, {%8,%9}, {%0,%1,%2,%3};"
        : "+f"(d[0]), "+f"(d[1]), "+f"(d[2]), "+f"(d[3])
        : "r"(a[0]), "r"(a[1]), "r"(a[2]), "r"(a[3]),
          "r"(b[0]), "r"(b[1]));
}

#define LDSM4(R, A) \
    asm volatile("ldmatrix.sync.aligned.m8n8.x4.shared.b16 {%0,%1,%2,%3}, [%4];" \
        : "=r"((R)[0]), "=r"((R)[1]), "=r"((R)[2]), "=r"((R)[3]) : "r"(A))

#define LDSM4T(R, A) \
    asm volatile("ldmatrix.sync.aligned.m8n8.x4.trans.shared.b16 {%0,%1,%2,%3}, [%4];" \
        : "=r"((R)[0]), "=r"((R)[1]), "=r"((R)[2]), "=r"((R)[3]) : "r"(A))

__device__ __forceinline__ void split2h(float x, __half& hi, __half& lo) {
    hi = __float2half_rn(x);
    lo = __float2half_rn(x - __half2float(hi));
}

__device__ __forceinline__ uint32_t packh2(float a, float b) {
    __half2 h = __floats2half2_rn(a, b);
    return *(uint32_t*)&h;
}

// ---------------------------------------------------------------------------
// Fused weight prep: transpose + x64 scale + exact fp16 2-term split.
// gate_up destination rows interleaved (gate i -> 2i, up i -> 2i+1).
// ---------------------------------------------------------------------------
#define TILES_PER_LAYER 43008
__global__ void prep_weights(const float* __restrict__ wqkv,
                             const float* __restrict__ wo,
                             const float* __restrict__ wgu,
                             const float* __restrict__ wdn,
                             __half* __restrict__ wth,
                             __half* __restrict__ wtl) {
    __shared__ float tile[32][33];
    int bid = blockIdx.x;
    int l = 0;
    if (bid >= TILES_PER_LAYER) { l = 1; bid -= TILES_PER_LAYER; }
    size_t loff = (size_t)l * WT_PER_L;

    const float* src;
    __half *hi, *lo;
    int K, N;
    int gu_mode = 0;
    if (bid < 5120) {
        src = wqkv + (size_t)l * Hc * QKVN;
        hi = wth + loff + WT_QKV_OFF; lo = wtl + loff + WT_QKV_OFF;
        K = Hc; N = QKVN;
    } else if (bid < 9216) {
        bid -= 5120;
        src = wo + (size_t)l * Hc * Hc;
        hi = wth + loff + WT_O_OFF; lo = wtl + loff + WT_O_OFF;
        K = Hc; N = Hc;
    } else if (bid < 31744) {
        bid -= 9216;
        src = wgu + (size_t)l * Hc * GUN;
        hi = wth + loff + WT_GU_OFF; lo = wtl + loff + WT_GU_OFF;
        K = Hc; N = GUN;
        gu_mode = 1;
    } else {
        bid -= 31744;
        src = wdn + (size_t)l * Ic * Hc;
        hi = wth + loff + WT_DN_OFF; lo = wtl + loff + WT_DN_OFF;
        K = Ic; N = Hc;
    }
    int tilesX = N / 32;
    int nb = (bid % tilesX) * 32;
    int kb = (bid / tilesX) * 32;

#pragma unroll
    for (int i = threadIdx.y; i < 32; i += 8)
        tile[i][threadIdx.x] = src[(size_t)(kb + i) * N + nb + threadIdx.x];
    __syncthreads();
#pragma unroll
    for (int i = threadIdx.y; i < 32; i += 8) {
        float v = tile[threadIdx.x][i] * WSCALE;
        __half h, lv;
        split2h(v, h, lv);
        int col = nb + i;
        if (gu_mode) col = (col < Ic) ? (2 * col) : (2 * (col - Ic) + 1);
        size_t idx = (size_t)col * K + kb + threadIdx.x;
        hi[idx] = h;
        lo[idx] = lv;
    }
}

// ---------------------------------------------------------------------------
// fp16 GEMM, templated on weight TERMS:
//   TERMS=2: C = (A @ (Whi+Wlo)^T)/64   (exact weights, 2 MMAs per k-step)
//   TERMS=1: C = (A @ Whi^T)/64         (fp16 weights,  1 MMA per k-step)
// If actout != nullptr: interleaved (gate,up) columns; epilogue computes
// silu(gate)*up -> fp16 actout[M, N/2].
// Block 128x128, BK=16, 256 threads (8 warps, 32x64 warp tiles).
// 4-stage cp.async pipeline (wait_group 2), ldmatrix fragment loads.
// ---------------------------------------------------------------------------
#define RPITCH 48
#define ARRB   (128 * RPITCH)
#define STAGEB (3 * ARRB)
#define GEMM_SMEM (4 * STAGEB)

template <int TERMS>
__global__ void __launch_bounds__(256, 2)
gemm_f16(const __half* __restrict__ A,
         const __half* __restrict__ Wh,
         const __half* __restrict__ Wl,
         float* __restrict__ C, const float* __restrict__ addend,
         __half* __restrict__ actout,
         int M, int N, int K) {
    extern __shared__ char smraw[];
    uint32_t sbase = smem_u32(smraw);

    const int tid  = threadIdx.x;
    const int warp = tid >> 5;
    const int lane = tid & 31;
    const int wm   = (warp >> 1) * 32;
    const int wn   = (warp & 1) * 64;
    const int grp  = lane >> 2;
    const int tig  = lane & 3;

    const int m0 = blockIdx.x * 128;
    const int n0 = blockIdx.y * 128;

    const int li = lane >> 3;
    const int lr = lane & 7;
    const uint32_t aoffl = (uint32_t)(((li & 1) * 8 + lr) * RPITCH + (li >> 1) * 16);
    const uint32_t boffl = (uint32_t)(((li >> 1) * 8 + lr) * RPITCH + (li & 1) * 16);

    const int r0   = tid >> 1;
    const int half = tid & 1;
    const uint32_t sdst = (uint32_t)(r0 * RPITCH + half * 16);
    const __half* pA  = A  + (size_t)(m0 + r0) * K + half * 8;
    const __half* pWh = Wh + (size_t)(n0 + r0) * K + half * 8;
    const __half* pWl = (TERMS == 2) ? (Wl + (size_t)(n0 + r0) * K + half * 8) : nullptr;

    const int nkt = K >> 4;

    float c[2][8][4];
#pragma unroll
    for (int mt = 0; mt < 2; mt++)
#pragma unroll
        for (int nt = 0; nt < 8; nt++)
#pragma unroll
            for (int i = 0; i < 4; i++) c[mt][nt][i] = 0.f;

#pragma unroll
    for (int s = 0; s < 3; s++) {
        uint32_t b = sbase + (uint32_t)s * STAGEB + sdst;
        int ko = s * 16;
        cp_async16(b,            pA  + ko);
        cp_async16(b + ARRB,     pWh + ko);
        if (TERMS == 2) cp_async16(b + 2 * ARRB, pWl + ko);
        CP_COMMIT();
    }

    for (int kt = 0; kt < nkt; kt++) {
        CP_WAIT2();
        __syncthreads();

        uint32_t sb = sbase + (uint32_t)(kt & 3) * STAGEB;

        uint32_t a[2][4];
#pragma unroll
        for (int mt = 0; mt < 2; mt++) {
            uint32_t aaddr = sb + (uint32_t)((wm + mt * 16) * RPITCH) + aoffl;
            LDSM4(a[mt], aaddr);
        }
#pragma unroll
        for (int nh = 0; nh < 2; nh++) {
            uint32_t wh[2][4], wl[2][4];
#pragma unroll
            for (int pq = 0; pq < 2; pq++) {
                uint32_t baddr = sb + ARRB +
                                 (uint32_t)((wn + nh * 32 + pq * 16) * RPITCH) + boffl;
                LDSM4(wh[pq], baddr);
                if (TERMS == 2) LDSM4(wl[pq], baddr + ARRB);
            }
#pragma unroll
            for (int mt = 0; mt < 2; mt++)
#pragma unroll
                for (int pq = 0; pq < 2; pq++)
#pragma unroll
                    for (int h = 0; h < 2; h++)
                        mma_f16(c[mt][nh * 4 + pq * 2 + h], a[mt], &wh[pq][h * 2]);
            if (TERMS == 2) {
#pragma unroll
                for (int mt = 0; mt < 2; mt++)
#pragma unroll
                    for (int pq = 0; pq < 2; pq++)
#pragma unroll
                        for (int h = 0; h < 2; h++)
                            mma_f16(c[mt][nh * 4 + pq * 2 + h], a[mt], &wl[pq][h * 2]);
            }
        }

        if (kt + 3 < nkt) {
            uint32_t b = sbase + (uint32_t)((kt + 3) & 3) * STAGEB + sdst;
            int ko = (kt + 3) * 16;
            cp_async16(b,            pA  + ko);
            cp_async16(b + ARRB,     pWh + ko);
            if (TERMS == 2) cp_async16(b + 2 * ARRB, pWl + ko);
        }
        CP_COMMIT();
    }

    if (actout) {
#pragma unroll
        for (int mt = 0; mt < 2; mt++) {
            int row = m0 + wm + mt * 16 + grp;
#pragma unroll
            for (int nt = 0; nt < 8; nt++) {
                int col = n0 + wn + nt * 8 + tig * 2;
                int pair = col >> 1;
                {
                    float g = c[mt][nt][0] * WINV;
                    float u = c[mt][nt][1] * WINV;
                    float sig = 1.0f / (1.0f + __expf(-g));
                    actout[(size_t)row * Ic + pair] = __float2half_rn(g * sig * u);
                }
                {
                    float g = c[mt][nt][2] * WINV;
                    float u = c[mt][nt][3] * WINV;
                    float sig = 1.0f / (1.0f + __expf(-g));
                    actout[(size_t)(row + 8) * Ic + pair] = __float2half_rn(g * sig * u);
                }
            }
        }
    } else {
#pragma unroll
        for (int mt = 0; mt < 2; mt++) {
            int row = m0 + wm + mt * 16 + grp;
#pragma unroll
            for (int nt = 0; nt < 8; nt++) {
                int col = n0 + wn + nt * 8 + tig * 2;
                size_t i0 = (size_t)row * N + col;
                size_t i1 = (size_t)(row + 8) * N + col;
                float2 v0 = make_float2(c[mt][nt][0] * WINV, c[mt][nt][1] * WINV);
                float2 v1 = make_float2(c[mt][nt][2] * WINV, c[mt][nt][3] * WINV);
                if (addend) {
                    float2 a0 = *(const float2*)(addend + i0);
                    float2 a1 = *(const float2*)(addend + i1);
                    v0.x += a0.x; v0.y += a0.y;
                    v1.x += a1.x; v1.y += a1.y;
                }
                *(float2*)(C + i0) = v0;
                *(float2*)(C + i1) = v1;
            }
        }
    }
}

// ---------------------------------------------------------------------------
// Embedding gather
// ---------------------------------------------------------------------------
__global__ void embed_kernel(const int* __restrict__ ids,
                             const float* __restrict__ embed,
                             float* __restrict__ res) {
    int t = blockIdx.x;
    int id = ids[t];
    const float4* src = (const float4*)(embed + (size_t)id * Hc);
    float4* dst = (float4*)(res + (size_t)t * Hc);
    for (int i = threadIdx.x; i < Hc / 4; i += blockDim.x)
        dst[i] = src[i];
}

// ---------------------------------------------------------------------------
// RMSNorm. Output fp32 and/or fp16.
// ---------------------------------------------------------------------------
__global__ void addnorm_kernel(const float* __restrict__ res,
                               const float* __restrict__ w,
                               float* __restrict__ outf,
                               __half* __restrict__ oh) {
    int t = blockIdx.x;
    int tid = threadIdx.x;
    const float* rp = res + (size_t)t * Hc;
    float vals[8];
    float ss = 0.f;
#pragma unroll
    for (int i = 0; i < 8; i++) {
        int idx = tid + i * 256;
        float v = rp[idx];
        vals[i] = v;
        ss += v * v;
    }
    __shared__ float warp_s[8];
#pragma unroll
    for (int off = 16; off > 0; off >>= 1)
        ss += __shfl_down_sync(0xffffffff, ss, off);
    if ((tid & 31) == 0) warp_s[tid >> 5] = ss;
    __syncthreads();
    if (tid < 8) {
        float v = warp_s[tid];
#pragma unroll
        for (int off = 4; off > 0; off >>= 1)
            v += __shfl_down_sync(0xff, v, off);
        if (tid == 0) warp_s[0] = v;
    }
    __syncthreads();
    float inv = rsqrtf(warp_s[0] * (1.0f / Hc) + EPSc);
#pragma unroll
    for (int i = 0; i < 8; i++) {
        int idx = tid + i * 256;
        float o = vals[i] * inv * w[idx];
        if (outf) outf[(size_t)t * Hc + idx] = o;
        if (oh)   oh[(size_t)t * Hc + idx] = __float2half_rn(o);
    }
}

// ---------------------------------------------------------------------------
// RoPE + split-fp16 scatter: Q (pre-scaled 0.125, exact split), K cache, V cache
// ---------------------------------------------------------------------------
__global__ void rope_kernel(const float* __restrict__ qkv,
                            const int* __restrict__ pos,
                            __half* __restrict__ qh, __half* __restrict__ ql,
                            __half* __restrict__ kh, __half* __restrict__ kl,
                            __half* __restrict__ vh, __half* __restrict__ vl) {
    int t = blockIdx.x;
    int b = t / Sc, s = t % Sc;
    int tid = threadIdx.x;
    float p = (float)pos[s];
    const float lt = logf(10000.f) / 32.f;

    for (int w = tid; w < (NHc + NKVc) * 32; w += blockDim.x) {
        int head = w / 32, j = w % 32;
        float ang = p * __expf(-(float)j * lt);
        float c = cosf(ang), sn = sinf(ang);
        if (head < NHc) {
            const float* base = qkv + (size_t)t * QKVN + head * HDc;
            float x1 = base[j], x2 = base[j + 32];
            float r1 = (x1 * c - x2 * sn) * 0.125f;
            float r2 = (x2 * c + x1 * sn) * 0.125f;
            size_t o = (size_t)t * Hc + head * HDc;
            __half h1, l1, h2, l2;
            split2h(r1, h1, l1);
            split2h(r2, h2, l2);
            qh[o + j] = h1;  ql[o + j] = l1;
            qh[o + j + 32] = h2;  ql[o + j + 32] = l2;
        } else {
            int hk = head - NHc;
            const float* base = qkv + (size_t)t * QKVN + NHc * HDc + hk * HDc;
            float x1 = base[j], x2 = base[j + 32];
            float r1 = x1 * c - x2 * sn;
            float r2 = x2 * c + x1 * sn;
            size_t o = (((size_t)(b * NKVc + hk)) * Sc + s) * HDc;
            __half h1, l1, h2, l2;
            split2h(r1, h1, l1);
            split2h(r2, h2, l2);
            kh[o + j] = h1;  kl[o + j] = l1;
            kh[o + j + 32] = h2;  kl[o + j + 32] = l2;
        }
    }
    for (int w = tid; w < NKVc * HDc; w += blockDim.x) {
        int hv = w / HDc, d = w % HDc;
        float v = qkv[(size_t)t * QKVN + (NHc + NKVc) * HDc + hv * HDc + d];
        size_t o = (((size_t)(b * NKVc + hv)) * Sc + s) * HDc + d;
        __half h1, l1;
        split2h(v, h1, l1);
        vh[o] = h1;  vl[o] = l1;
    }
}

// ---------------------------------------------------------------------------
// Flash attention on fp16 MMA. One block = 64 queries of one (b, head).
// 4 warps x 16 rows. QK: 3-term split (exact). PV: P fp16 x V 2-term split.
// ---------------------------------------------------------------------------
#define FPITCHB 144
#define FARR    (64 * FPITCHB)
#define FBUF    (4 * FARR)
#define FLASH_SMEM (2 * FBUF)

__global__ void __launch_bounds__(128)
flash_mma(const __half* __restrict__ qhg, const __half* __restrict__ qlg,
          const __half* __restrict__ khg, const __half* __restrict__ klg,
          const __half* __restrict__ vhg, const __half* __restrict__ vlg,
          __half* __restrict__ aout) {
    extern __shared__ char smraw[];
    uint32_t sbase = smem_u32(smraw);

    const int qb = blockIdx.x;
    const int h  = blockIdx.y;
    const int b  = blockIdx.z;
    const int hkv = h / (NHc / NKVc);
    const int tid = threadIdx.x;
    const int w   = tid >> 5;
    const int lane = tid & 31;
    const int grp = lane >> 2;
    const int tig = lane & 3;
    const int li = lane >> 3;
    const int lr = lane & 7;
    const uint32_t boffl = (uint32_t)(((li >> 1) * 8 + lr) * FPITCHB + (li & 1) * 16);
    const uint32_t voffl = (uint32_t)(((li & 1) * 8 + lr) * FPITCHB + (li >> 1) * 16);

    uint32_t qfh[4][4], qfl[4][4];
    {
        int row0 = b * Sc + qb * 64 + w * 16 + grp;
#pragma unroll
        for (int kt = 0; kt < 4; kt++) {
#pragma unroll
            for (int i = 0; i < 4; i++) {
                int row = row0 + (i & 1) * 8;
                int col = h * HDc + kt * 16 + (i >> 1) * 8 + tig * 2;
                qfh[kt][i] = *(const uint32_t*)&qhg[(size_t)row * Hc + col];
                qfl[kt][i] = *(const uint32_t*)&qlg[(size_t)row * Hc + col];
            }
        }
    }

    float o[8][4];
#pragma unroll
    for (int dn = 0; dn < 8; dn++)
#pragma unroll
        for (int i = 0; i < 4; i++) o[dn][i] = 0.f;
    float m0 = -1e30f, m1 = -1e30f, l0 = 0.f, l1 = 0.f;

    const size_t kvbase = ((size_t)(b * NKVc + hkv)) * Sc;

    {
        uint32_t bb = sbase;
#pragma unroll
        for (int i = 0; i < 4; i++) {
            int chunk = tid + i * 128;
            int r = chunk >> 3, cc = chunk & 7;
            uint32_t so = (uint32_t)(r * FPITCHB + cc * 16);
            size_t go = (kvbase + r) * HDc + cc * 8;
            cp_async16(bb + so,            khg + go);
            cp_async16(bb + FARR + so,     klg + go);
            cp_async16(bb + 2 * FARR + so, vhg + go);
            cp_async16(bb + 3 * FARR + so, vlg + go);
        }
        CP_COMMIT();
    }

    for (int kb = 0; kb <= qb; kb++) {
        CP_WAIT0();
        __syncthreads();

        if (kb + 1 <= qb) {
            uint32_t bb = sbase + (uint32_t)((kb + 1) & 1) * FBUF;
#pragma unroll
            for (int i = 0; i < 4; i++) {
                int chunk = tid + i * 128;
                int r = chunk >> 3, cc = chunk & 7;
                uint32_t so = (uint32_t)(r * FPITCHB + cc * 16);
                size_t go = (kvbase + (kb + 1) * 64 + r) * HDc + cc * 8;
                cp_async16(bb + so,            khg + go);
                cp_async16(bb + FARR + so,     klg + go);
                cp_async16(bb + 2 * FARR + so, vhg + go);
                cp_async16(bb + 3 * FARR + so, vlg + go);
            }
            CP_COMMIT();
        }

        uint32_t sb = sbase + (uint32_t)(kb & 1) * FBUF;

        float s[8][4];
#pragma unroll
        for (int nt = 0; nt < 8; nt++)
#pragma unroll
            for (int i = 0; i < 4; i++) s[nt][i] = 0.f;

#pragma unroll
        for (int kt = 0; kt < 4; kt++) {
            uint32_t kfh[4][4], kfl[4][4];
#pragma unroll
            for (int kg = 0; kg < 4; kg++) {
                uint32_t addr = sb + (uint32_t)(kg * 16 * FPITCHB) + (uint32_t)(kt * 32) + boffl;
                LDSM4(kfh[kg], addr);
                LDSM4(kfl[kg], addr + FARR);
            }
#pragma unroll
            for (int kg = 0; kg < 4; kg++)
#pragma unroll
                for (int hh = 0; hh < 2; hh++)
                    mma_f16(s[kg * 2 + hh], qfh[kt], &kfh[kg][hh * 2]);
#pragma unroll
            for (int kg = 0; kg < 4; kg++)
#pragma unroll
                for (int hh = 0; hh < 2; hh++)
                    mma_f16(s[kg * 2 + hh], qfh[kt], &kfl[kg][hh * 2]);
#pragma unroll
            for (int kg = 0; kg < 4; kg++)
#pragma unroll
                for (int hh = 0; hh < 2; hh++)
                    mma_f16(s[kg * 2 + hh], qfl[kt], &kfh[kg][hh * 2]);
        }

        if (kb == qb) {
            int rl0 = w * 16 + grp;
            int rl1 = rl0 + 8;
#pragma unroll
            for (int nt = 0; nt < 8; nt++) {
                int cl = nt * 8 + tig * 2;
                if (cl     > rl0) s[nt][0] = -1e30f;
                if (cl + 1 > rl0) s[nt][1] = -1e30f;
                if (cl     > rl1) s[nt][2] = -1e30f;
                if (cl + 1 > rl1) s[nt][3] = -1e30f;
            }
        }

        {
            float mx0 = -1e30f, mx1 = -1e30f;
#pragma unroll
            for (int nt = 0; nt < 8; nt++) {
                mx0 = fmaxf(mx0, fmaxf(s[nt][0], s[nt][1]));
                mx1 = fmaxf(mx1, fmaxf(s[nt][2], s[nt][3]));
            }
            mx0 = fmaxf(mx0, __shfl_xor_sync(0xffffffffu, mx0, 1));
            mx0 = fmaxf(mx0, __shfl_xor_sync(0xffffffffu, mx0, 2));
            mx1 = fmaxf(mx1, __shfl_xor_sync(0xffffffffu, mx1, 1));
            mx1 = fmaxf(mx1, __shfl_xor_sync(0xffffffffu, mx1, 2));
            float mn0 = fmaxf(m0, mx0);
            float mn1 = fmaxf(m1, mx1);
            float a0 = __expf(m0 - mn0);
            float a1 = __expf(m1 - mn1);
            float su0 = 0.f, su1 = 0.f;
#pragma unroll
            for (int nt = 0; nt < 8; nt++) {
                s[nt][0] = __expf(s[nt][0] - mn0); su0 += s[nt][0];
                s[nt][1] = __expf(s[nt][1] - mn0); su0 += s[nt][1];
                s[nt][2] = __expf(s[nt][2] - mn1); su1 += s[nt][2];
                s[nt][3] = __expf(s[nt][3] - mn1); su1 += s[nt][3];
            }
            su0 += __shfl_xor_sync(0xffffffffu, su0, 1);
            su0 += __shfl_xor_sync(0xffffffffu, su0, 2);
            su1 += __shfl_xor_sync(0xffffffffu, su1, 1);
            su1 += __shfl_xor_sync(0xffffffffu, su1, 2);
            l0 = l0 * a0 + su0;
            l1 = l1 * a1 + su1;
            m0 = mn0;
            m1 = mn1;
#pragma unroll
            for (int dn = 0; dn < 8; dn++) {
                o[dn][0] *= a0; o[dn][1] *= a0;
                o[dn][2] *= a1; o[dn][3] *= a1;
            }
        }

#pragma unroll
        for (int kt = 0; kt < 4; kt++) {
            uint32_t a[4];
            a[0] = packh2(s[2 * kt][0],     s[2 * kt][1]);
            a[1] = packh2(s[2 * kt][2],     s[2 * kt][3]);
            a[2] = packh2(s[2 * kt + 1][0], s[2 * kt + 1][1]);
            a[3] = packh2(s[2 * kt + 1][2], s[2 * kt + 1][3]);
            uint32_t vfh[4][4], vfl[4][4];
#pragma unroll
            for (int db = 0; db < 4; db++) {
                uint32_t addr = sb + 2 * FARR + (uint32_t)(kt * 16 * FPITCHB) + (uint32_t)(db * 32) + voffl;
                LDSM4T(vfh[db], addr);
                LDSM4T(vfl[db], addr + FARR);
            }
#pragma unroll
            for (int db = 0; db < 4; db++)
#pragma unroll
                for (int hh = 0; hh < 2; hh++)
                    mma_f16(o[db * 2 + hh], a, &vfh[db][hh * 2]);
#pragma unroll
            for (int db = 0; db < 4; db++)
#pragma unroll
                for (int hh = 0; hh < 2; hh++)
                    mma_f16(o[db * 2 + hh], a, &vfl[db][hh * 2]);
        }
    }

    {
        float i0 = 1.0f / l0;
        float i1 = 1.0f / l1;
        size_t row0 = (size_t)(b * Sc + qb * 64 + w * 16 + grp);
#pragma unroll
        for (int dn = 0; dn < 8; dn++) {
            int col = h * HDc + dn * 8 + tig * 2;
            __half2 p0 = __floats2half2_rn(o[dn][0] * i0, o[dn][1] * i0);
            __half2 p1 = __floats2half2_rn(o[dn][2] * i1, o[dn][3] * i1);
            *(__half2*)&aout[row0 * Hc + col] = p0;
            *(__half2*)&aout[(row0 + 8) * Hc + col] = p1;
        }
    }
}

// ---------------------------------------------------------------------------
// Launch
// ---------------------------------------------------------------------------
extern "C" void kernel_launch(void* const* d_in, const int* in_sizes, int n_in,
                              void* d_out, int out_size) {
    const int*   input_ids = (const int*)d_in[0];
    const int*   positions = (const int*)d_in[1];
    const float* embed     = (const float*)d_in[2];
    const float* w_qkv     = (const float*)d_in[3];
    const float* w_o       = (const float*)d_in[4];
    const float* w_gate_up = (const float*)d_in[5];
    const float* w_down    = (const float*)d_in[6];
    const float* ln1_w     = (const float*)d_in[7];
    const float* ln2_w     = (const float*)d_in[8];
    const float* norm_w    = (const float*)d_in[9];
    float* out = (float*)d_out;

    float *res, *qkv;
    __half *hn, *at, *ac, *wh, *wl, *qh, *ql, *kh, *kl, *vh, *vl;
    cudaGetSymbolAddress((void**)&res,  g_res);
    cudaGetSymbolAddress((void**)&qkv,  g_qkv);
    cudaGetSymbolAddress((void**)&hn,   g_hn);
    cudaGetSymbolAddress((void**)&at,   g_at);
    cudaGetSymbolAddress((void**)&ac,   g_ac);
    cudaGetSymbolAddress((void**)&wh,   g_wh);
    cudaGetSymbolAddress((void**)&wl,   g_wl);
    cudaGetSymbolAddress((void**)&qh,   g_qh);
    cudaGetSymbolAddress((void**)&ql,   g_ql);
    cudaGetSymbolAddress((void**)&kh,   g_kh);
    cudaGetSymbolAddress((void**)&kl,   g_kl);
    cudaGetSymbolAddress((void**)&vh,   g_vh);
    cudaGetSymbolAddress((void**)&vl,   g_vl);

    cudaFuncSetAttribute(flash_mma, cudaFuncAttributeMaxDynamicSharedMemorySize, FLASH_SMEM);
    cudaFuncSetAttribute(gemm_f16<2>, cudaFuncAttributeMaxDynamicSharedMemorySize, GEMM_SMEM);
    cudaFuncSetAttribute(gemm_f16<1>, cudaFuncAttributeMaxDynamicSharedMemorySize, GEMM_SMEM);

    prep_weights<<<2 * TILES_PER_LAYER, dim3(32, 8)>>>(
        w_qkv, w_o, w_gate_up, w_down, wh, wl);

    embed_kernel<<<Tc, 256>>>(input_ids, embed, res);

    for (int l = 0; l < Lc; l++) {
        __half* whl = wh + (size_t)l * WT_PER_L;
        __half* wll = wl + (size_t)l * WT_PER_L;

        addnorm_kernel<<<Tc, 256>>>(res, ln1_w + (size_t)l * Hc, nullptr, hn);

        gemm_f16<2><<<dim3(Tc / 128, QKVN / 128), 256, GEMM_SMEM>>>(
            hn, whl + WT_QKV_OFF, wll + WT_QKV_OFF, qkv, nullptr, nullptr,
            Tc, QKVN, Hc);

        rope_kernel<<<Tc, 128>>>(qkv, positions, qh, ql, kh, kl, vh, vl);

        flash_mma<<<dim3(Sc / 64, NHc, Bc), 128, FLASH_SMEM>>>(
            qh, ql, kh, kl, vh, vl, at);

        gemm_f16<2><<<dim3(Tc / 128, Hc / 128), 256, GEMM_SMEM>>>(
            at, whl + WT_O_OFF, wll + WT_O_OFF, res, res, nullptr,
            Tc, Hc, Hc);

        addnorm_kernel<<<Tc, 256>>>(res, ln2_w + (size_t)l * Hc, nullptr, hn);

        // gate_up: 1-term fp16 weights (error budget spent here; 52% of GEMM flops)
        gemm_f16<1><<<dim3(Tc / 128, GUN / 128), 256, GEMM_SMEM>>>(
            hn, whl + WT_GU_OFF, nullptr, nullptr, nullptr, ac,
            Tc, GUN, Hc);

        gemm_f16<2><<<dim3(Tc / 128, Hc / 128), 256, GEMM_SMEM>>>(
            ac, whl + WT_DN_OFF, wll + WT_DN_OFF, res, res, nullptr,
            Tc, Hc, Ic);
    }

    addnorm_kernel<<<Tc, 256>>>(res, norm_w, out, nullptr);
}

// round 12
// speedup vs baseline: 2.3475x; 1.1009x over previous
#include <cuda_runtime.h>
#include <cuda_fp16.h>
#include <math.h>
#include <stdint.h>

// ---------------------------------------------------------------------------
// Model constants
// ---------------------------------------------------------------------------
#define Lc 2
#define Hc 2048
#define NHc 32
#define NKVc 4
#define HDc 64
#define Ic 5632
#define Bc 2
#define Sc 1024
#define Tc (Bc * Sc)                   // 2048 tokens
#define QKVN ((NHc + 2 * NKVc) * HDc)  // 2560
#define GUN (2 * Ic)                   // 11264
#define EPSc 1e-5f
#define WSCALE 64.0f
#define WINV   0.015625f               // 1/64
#define ROPE_LT 0.2878231366f          // ln(10000)/32

// ---------------------------------------------------------------------------
// Scratch (static device globals; no allocation allowed)
// ---------------------------------------------------------------------------
__device__ float g_res [Tc * Hc];

// fp16 activations (GEMM A operands)
__device__ __half g_hn [Tc * Hc];
__device__ __half g_at [Tc * Hc];
__device__ __half g_ac [(size_t)Tc * Ic];

// split fp16 Q (pre-scaled by 0.125) and KV caches
__device__ __half g_qh [Tc * Hc];
__device__ __half g_ql [Tc * Hc];
__device__ __half g_kh [Bc * NKVc * Sc * HDc];
__device__ __half g_kl [Bc * NKVc * Sc * HDc];
__device__ __half g_vh [Bc * NKVc * Sc * HDc];
__device__ __half g_vl [Bc * NKVc * Sc * HDc];

// Transposed split weights (x64 scaled, fp16 hi+lo exact 2-term):
// per layer [qkv_t(QKVN,H) | o_t(H,H) | gu_t(GUN,H, gate/up interleaved) | down_t(H,I)]
#define WT_QKV_OFF 0
#define WT_O_OFF   ((size_t)QKVN * Hc)
#define WT_GU_OFF  (WT_O_OFF + (size_t)Hc * Hc)
#define WT_DN_OFF  (WT_GU_OFF + (size_t)GUN * Hc)
#define WT_PER_L   (WT_DN_OFF + (size_t)Hc * Ic)
__device__ __half g_wh[2 * WT_PER_L];
__device__ __half g_wl[2 * WT_PER_L];

// ---------------------------------------------------------------------------
// Helpers
// ---------------------------------------------------------------------------
__device__ __forceinline__ uint32_t smem_u32(const void* p) {
    uint32_t a;
    asm("{ .reg .u64 t; cvta.to.shared.u64 t, %1; cvt.u32.u64 %0, t; }"
        : "=r"(a) : "l"(p));
    return a;
}

__device__ __forceinline__ void cp_async16(uint32_t smem_addr, const void* gptr) {
    asm volatile("cp.async.cg.shared.global [%0], [%1], 16;"
                 :: "r"(smem_addr), "l"(gptr) : "memory");
}
#define CP_COMMIT() asm volatile("cp.async.commit_group;" ::: "memory")
#define CP_WAIT0()  asm volatile("cp.async.wait_group 0;" ::: "memory")
#define CP_WAIT2()  asm volatile("cp.async.wait_group 2;" ::: "memory")

__device__ __forceinline__ void mma_f16(float* d, const uint32_t* a, const uint32_t* b) {
    asm volatile(
        "mma.sync.aligned.m16n8k16.row.col.f32.f16.f16.f32 "
        "{%0,%1,%2,%3}, {%4,%5,%6,%7}, {%8,%9}, {%0,%1,%2,%3};"
        : "+f"(d[0]), "+f"(d[1]), "+f"(d[2]), "+f"(d[3])
        : "r"(a[0]), "r"(a[1]), "r"(a[2]), "r"(a[3]),
          "r"(b[0]), "r"(b[1]));
}

#define LDSM4(R, A) \
    asm volatile("ldmatrix.sync.aligned.m8n8.x4.shared.b16 {%0,%1,%2,%3}, [%4];" \
        : "=r"((R)[0]), "=r"((R)[1]), "=r"((R)[2]), "=r"((R)[3]) : "r"(A))

#define LDSM4T(R, A) \
    asm volatile("ldmatrix.sync.aligned.m8n8.x4.trans.shared.b16 {%0,%1,%2,%3}, [%4];" \
        : "=r"((R)[0]), "=r"((R)[1]), "=r"((R)[2]), "=r"((R)[3]) : "r"(A))

__device__ __forceinline__ void split2h(float x, __half& hi, __half& lo) {
    hi = __float2half_rn(x);
    lo = __float2half_rn(x - __half2float(hi));
}

__device__ __forceinline__ uint32_t packh2(float a, float b) {
    __half2 h = __floats2half2_rn(a, b);
    return *(uint32_t*)&h;
}

// ---------------------------------------------------------------------------
// Fused weight prep: transpose + x64 scale + exact fp16 2-term split.
// gate_up destination rows interleaved (gate i -> 2i, up i -> 2i+1).
// ---------------------------------------------------------------------------
#define TILES_PER_LAYER 43008
__global__ void prep_weights(const float* __restrict__ wqkv,
                             const float* __restrict__ wo,
                             const float* __restrict__ wgu,
                             const float* __restrict__ wdn,
                             __half* __restrict__ wth,
                             __half* __restrict__ wtl) {
    __shared__ float tile[32][33];
    int bid = blockIdx.x;
    int l = 0;
    if (bid >= TILES_PER_LAYER) { l = 1; bid -= TILES_PER_LAYER; }
    size_t loff = (size_t)l * WT_PER_L;

    const float* src;
    __half *hi, *lo;
    int K, N;
    int gu_mode = 0;
    if (bid < 5120) {
        src = wqkv + (size_t)l * Hc * QKVN;
        hi = wth + loff + WT_QKV_OFF; lo = wtl + loff + WT_QKV_OFF;
        K = Hc; N = QKVN;
    } else if (bid < 9216) {
        bid -= 5120;
        src = wo + (size_t)l * Hc * Hc;
        hi = wth + loff + WT_O_OFF; lo = wtl + loff + WT_O_OFF;
        K = Hc; N = Hc;
    } else if (bid < 31744) {
        bid -= 9216;
        src = wgu + (size_t)l * Hc * GUN;
        hi = wth + loff + WT_GU_OFF; lo = wtl + loff + WT_GU_OFF;
        K = Hc; N = GUN;
        gu_mode = 1;
    } else {
        bid -= 31744;
        src = wdn + (size_t)l * Ic * Hc;
        hi = wth + loff + WT_DN_OFF; lo = wtl + loff + WT_DN_OFF;
        K = Ic; N = Hc;
    }
    int tilesX = N / 32;
    int nb = (bid % tilesX) * 32;
    int kb = (bid / tilesX) * 32;

#pragma unroll
    for (int i = threadIdx.y; i < 32; i += 8)
        tile[i][threadIdx.x] = src[(size_t)(kb + i) * N + nb + threadIdx.x];
    __syncthreads();
#pragma unroll
    for (int i = threadIdx.y; i < 32; i += 8) {
        float v = tile[threadIdx.x][i] * WSCALE;
        __half h, lv;
        split2h(v, h, lv);
        int col = nb + i;
        if (gu_mode) col = (col < Ic) ? (2 * col) : (2 * (col - Ic) + 1);
        size_t idx = (size_t)col * K + kb + threadIdx.x;
        hi[idx] = h;
        lo[idx] = lv;
    }
}

// ---------------------------------------------------------------------------
// fp16 GEMM, templated on weight TERMS (2 = exact split, 1 = fp16 weights).
// Epilogue modes:
//   actout != nullptr : interleaved (gate,up) cols -> silu(g)*u fp16
//   qh     != nullptr : QKV mode -> RoPE + split-fp16 scatter to q/k/v caches
//   else              : fp32 C (+ optional addend)
// Block 128x128, BK=16, 256 threads, 4-stage cp.async, ldmatrix loads.
// ---------------------------------------------------------------------------
#define RPITCH 48
#define ARRB   (128 * RPITCH)
#define STAGEB (3 * ARRB)
#define GEMM_SMEM (4 * STAGEB)

template <int TERMS>
__global__ void __launch_bounds__(256, 2)
gemm_f16(const __half* __restrict__ A,
         const __half* __restrict__ Wh,
         const __half* __restrict__ Wl,
         float* __restrict__ C, const float* __restrict__ addend,
         __half* __restrict__ actout,
         __half* __restrict__ qh, __half* __restrict__ ql,
         __half* __restrict__ kh, __half* __restrict__ kl,
         __half* __restrict__ vh, __half* __restrict__ vl,
         const int* __restrict__ positions,
         int M, int N, int K) {
    extern __shared__ char smraw[];
    uint32_t sbase = smem_u32(smraw);

    const int tid  = threadIdx.x;
    const int warp = tid >> 5;
    const int lane = tid & 31;
    const int wm   = (warp >> 1) * 32;
    const int wn   = (warp & 1) * 64;
    const int grp  = lane >> 2;
    const int tig  = lane & 3;

    const int m0 = blockIdx.x * 128;
    const int n0 = blockIdx.y * 128;

    const int li = lane >> 3;
    const int lr = lane & 7;
    const uint32_t aoffl = (uint32_t)(((li & 1) * 8 + lr) * RPITCH + (li >> 1) * 16);
    const uint32_t boffl = (uint32_t)(((li >> 1) * 8 + lr) * RPITCH + (li & 1) * 16);

    const int r0   = tid >> 1;
    const int half = tid & 1;
    const uint32_t sdst = (uint32_t)(r0 * RPITCH + half * 16);
    const __half* pA  = A  + (size_t)(m0 + r0) * K + half * 8;
    const __half* pWh = Wh + (size_t)(n0 + r0) * K + half * 8;
    const __half* pWl = (TERMS == 2) ? (Wl + (size_t)(n0 + r0) * K + half * 8) : nullptr;

    const int nkt = K >> 4;

    float c[2][8][4];
#pragma unroll
    for (int mt = 0; mt < 2; mt++)
#pragma unroll
        for (int nt = 0; nt < 8; nt++)
#pragma unroll
            for (int i = 0; i < 4; i++) c[mt][nt][i] = 0.f;

#pragma unroll
    for (int s = 0; s < 3; s++) {
        uint32_t b = sbase + (uint32_t)s * STAGEB + sdst;
        int ko = s * 16;
        cp_async16(b,            pA  + ko);
        cp_async16(b + ARRB,     pWh + ko);
        if (TERMS == 2) cp_async16(b + 2 * ARRB, pWl + ko);
        CP_COMMIT();
    }

    for (int kt = 0; kt < nkt; kt++) {
        CP_WAIT2();
        __syncthreads();

        uint32_t sb = sbase + (uint32_t)(kt & 3) * STAGEB;

        uint32_t a[2][4];
#pragma unroll
        for (int mt = 0; mt < 2; mt++) {
            uint32_t aaddr = sb + (uint32_t)((wm + mt * 16) * RPITCH) + aoffl;
            LDSM4(a[mt], aaddr);
        }
#pragma unroll
        for (int nh = 0; nh < 2; nh++) {
            uint32_t wh[2][4], wl[2][4];
#pragma unroll
            for (int pq = 0; pq < 2; pq++) {
                uint32_t baddr = sb + ARRB +
                                 (uint32_t)((wn + nh * 32 + pq * 16) * RPITCH) + boffl;
                LDSM4(wh[pq], baddr);
                if (TERMS == 2) LDSM4(wl[pq], baddr + ARRB);
            }
#pragma unroll
            for (int mt = 0; mt < 2; mt++)
#pragma unroll
                for (int pq = 0; pq < 2; pq++)
#pragma unroll
                    for (int h = 0; h < 2; h++)
                        mma_f16(c[mt][nh * 4 + pq * 2 + h], a[mt], &wh[pq][h * 2]);
            if (TERMS == 2) {
#pragma unroll
                for (int mt = 0; mt < 2; mt++)
#pragma unroll
                    for (int pq = 0; pq < 2; pq++)
#pragma unroll
                        for (int h = 0; h < 2; h++)
                            mma_f16(c[mt][nh * 4 + pq * 2 + h], a[mt], &wl[pq][h * 2]);
            }
        }

        if (kt + 3 < nkt) {
            uint32_t b = sbase + (uint32_t)((kt + 3) & 3) * STAGEB + sdst;
            int ko = (kt + 3) * 16;
            cp_async16(b,            pA  + ko);
            cp_async16(b + ARRB,     pWh + ko);
            if (TERMS == 2) cp_async16(b + 2 * ARRB, pWl + ko);
        }
        CP_COMMIT();
    }

    if (actout) {
        // interleaved (gate, up) pairs -> silu(g)*u
#pragma unroll
        for (int mt = 0; mt < 2; mt++) {
            int row = m0 + wm + mt * 16 + grp;
#pragma unroll
            for (int nt = 0; nt < 8; nt++) {
                int col = n0 + wn + nt * 8 + tig * 2;
                int pair = col >> 1;
                {
                    float g = c[mt][nt][0] * WINV;
                    float u = c[mt][nt][1] * WINV;
                    float sig = 1.0f / (1.0f + __expf(-g));
                    actout[(size_t)row * Ic + pair] = __float2half_rn(g * sig * u);
                }
                {
                    float g = c[mt][nt][2] * WINV;
                    float u = c[mt][nt][3] * WINV;
                    float sig = 1.0f / (1.0f + __expf(-g));
                    actout[(size_t)(row + 8) * Ic + pair] = __float2half_rn(g * sig * u);
                }
            }
        }
    } else if (qh) {
        // QKV mode: RoPE + split-fp16 scatter. Each warp's 64-col span is one
        // head; the rotation pair (j, j+32) lives in (nt, nt+4) of this thread.
        int head64 = n0 + wn;
#pragma unroll
        for (int mt = 0; mt < 2; mt++) {
#pragma unroll
            for (int r = 0; r < 2; r++) {
                int tok = m0 + wm + mt * 16 + grp + r * 8;
                int bb = tok / Sc;
                int ss = tok - bb * Sc;
                float p = (float)positions[ss];
                if (head64 < NHc * HDc) {
                    int head = head64 >> 6;
                    size_t base = (size_t)tok * Hc + head * HDc;
#pragma unroll
                    for (int nt = 0; nt < 4; nt++) {
#pragma unroll
                        for (int e = 0; e < 2; e++) {
                            int j = nt * 8 + tig * 2 + e;
                            float x1 = c[mt][nt][r * 2 + e] * WINV;
                            float x2 = c[mt][nt + 4][r * 2 + e] * WINV;
                            float ang = p * __expf(-(float)j * ROPE_LT);
                            float cc = cosf(ang), sn = sinf(ang);
                            float r1 = (x1 * cc - x2 * sn) * 0.125f;
                            float r2 = (x2 * cc + x1 * sn) * 0.125f;
                            __half h1, l1, h2, l2;
                            split2h(r1, h1, l1);
                            split2h(r2, h2, l2);
                            qh[base + j] = h1;       ql[base + j] = l1;
                            qh[base + j + 32] = h2;  ql[base + j + 32] = l2;
                        }
                    }
                } else if (head64 < (NHc + NKVc) * HDc) {
                    int hk = (head64 - NHc * HDc) >> 6;
                    size_t base = (((size_t)(bb * NKVc + hk)) * Sc + ss) * HDc;
#pragma unroll
                    for (int nt = 0; nt < 4; nt++) {
#pragma unroll
                        for (int e = 0; e < 2; e++) {
                            int j = nt * 8 + tig * 2 + e;
                            float x1 = c[mt][nt][r * 2 + e] * WINV;
                            float x2 = c[mt][nt + 4][r * 2 + e] * WINV;
                            float ang = p * __expf(-(float)j * ROPE_LT);
                            float cc = cosf(ang), sn = sinf(ang);
                            float r1 = x1 * cc - x2 * sn;
                            float r2 = x2 * cc + x1 * sn;
                            __half h1, l1, h2, l2;
                            split2h(r1, h1, l1);
                            split2h(r2, h2, l2);
                            kh[base + j] = h1;       kl[base + j] = l1;
                            kh[base + j + 32] = h2;  kl[base + j + 32] = l2;
                        }
                    }
                } else {
                    int hv = (head64 - (NHc + NKVc) * HDc) >> 6;
                    size_t base = (((size_t)(bb * NKVc + hv)) * Sc + ss) * HDc;
#pragma unroll
                    for (int nt = 0; nt < 8; nt++) {
#pragma unroll
                        for (int e = 0; e < 2; e++) {
                            int d = nt * 8 + tig * 2 + e;
                            float v = c[mt][nt][r * 2 + e] * WINV;
                            __half h1, l1;
                            split2h(v, h1, l1);
                            vh[base + d] = h1;  vl[base + d] = l1;
                        }
                    }
                }
            }
        }
    } else {
#pragma unroll
        for (int mt = 0; mt < 2; mt++) {
            int row = m0 + wm + mt * 16 + grp;
#pragma unroll
            for (int nt = 0; nt < 8; nt++) {
                int col = n0 + wn + nt * 8 + tig * 2;
                size_t i0 = (size_t)row * N + col;
                size_t i1 = (size_t)(row + 8) * N + col;
                float2 v0 = make_float2(c[mt][nt][0] * WINV, c[mt][nt][1] * WINV);
                float2 v1 = make_float2(c[mt][nt][2] * WINV, c[mt][nt][3] * WINV);
                if (addend) {
                    float2 a0 = *(const float2*)(addend + i0);
                    float2 a1 = *(const float2*)(addend + i1);
                    v0.x += a0.x; v0.y += a0.y;
                    v1.x += a1.x; v1.y += a1.y;
                }
                *(float2*)(C + i0) = v0;
                *(float2*)(C + i1) = v1;
            }
        }
    }
}

// ---------------------------------------------------------------------------
// Embedding gather
// ---------------------------------------------------------------------------
__global__ void embed_kernel(const int* __restrict__ ids,
                             const float* __restrict__ embed,
                             float* __restrict__ res) {
    int t = blockIdx.x;
    int id = ids[t];
    const float4* src = (const float4*)(embed + (size_t)id * Hc);
    float4* dst = (float4*)(res + (size_t)t * Hc);
    for (int i = threadIdx.x; i < Hc / 4; i += blockDim.x)
        dst[i] = src[i];
}

// ---------------------------------------------------------------------------
// RMSNorm. Output fp32 and/or fp16.
// ---------------------------------------------------------------------------
__global__ void addnorm_kernel(const float* __restrict__ res,
                               const float* __restrict__ w,
                               float* __restrict__ outf,
                               __half* __restrict__ oh) {
    int t = blockIdx.x;
    int tid = threadIdx.x;
    const float* rp = res + (size_t)t * Hc;
    float vals[8];
    float ss = 0.f;
#pragma unroll
    for (int i = 0; i < 8; i++) {
        int idx = tid + i * 256;
        float v = rp[idx];
        vals[i] = v;
        ss += v * v;
    }
    __shared__ float warp_s[8];
#pragma unroll
    for (int off = 16; off > 0; off >>= 1)
        ss += __shfl_down_sync(0xffffffff, ss, off);
    if ((tid & 31) == 0) warp_s[tid >> 5] = ss;
    __syncthreads();
    if (tid < 8) {
        float v = warp_s[tid];
#pragma unroll
        for (int off = 4; off > 0; off >>= 1)
            v += __shfl_down_sync(0xff, v, off);
        if (tid == 0) warp_s[0] = v;
    }
    __syncthreads();
    float inv = rsqrtf(warp_s[0] * (1.0f / Hc) + EPSc);
#pragma unroll
    for (int i = 0; i < 8; i++) {
        int idx = tid + i * 256;
        float o = vals[i] * inv * w[idx];
        if (outf) outf[(size_t)t * Hc + idx] = o;
        if (oh)   oh[(size_t)t * Hc + idx] = __float2half_rn(o);
    }
}

// ---------------------------------------------------------------------------
// Flash attention on fp16 MMA. One block = 64 queries of one (b, head).
// QK: 3-term split (exact). PV: P 2-term split x V 2-term split (3 MMA terms).
// Heavy blocks (large qb) scheduled first.
// ---------------------------------------------------------------------------
#define FPITCHB 144
#define FARR    (64 * FPITCHB)
#define FBUF    (4 * FARR)
#define FLASH_SMEM (2 * FBUF)

__global__ void __launch_bounds__(128)
flash_mma(const __half* __restrict__ qhg, const __half* __restrict__ qlg,
          const __half* __restrict__ khg, const __half* __restrict__ klg,
          const __half* __restrict__ vhg, const __half* __restrict__ vlg,
          __half* __restrict__ aout) {
    extern __shared__ char smraw[];
    uint32_t sbase = smem_u32(smraw);

    const int qb = (int)gridDim.x - 1 - (int)blockIdx.x;   // heavy-first
    const int h  = blockIdx.y;
    const int b  = blockIdx.z;
    const int hkv = h / (NHc / NKVc);
    const int tid = threadIdx.x;
    const int w   = tid >> 5;
    const int lane = tid & 31;
    const int grp = lane >> 2;
    const int tig = lane & 3;
    const int li = lane >> 3;
    const int lr = lane & 7;
    const uint32_t boffl = (uint32_t)(((li >> 1) * 8 + lr) * FPITCHB + (li & 1) * 16);
    const uint32_t voffl = (uint32_t)(((li & 1) * 8 + lr) * FPITCHB + (li >> 1) * 16);

    uint32_t qfh[4][4], qfl[4][4];
    {
        int row0 = b * Sc + qb * 64 + w * 16 + grp;
#pragma unroll
        for (int kt = 0; kt < 4; kt++) {
#pragma unroll
            for (int i = 0; i < 4; i++) {
                int row = row0 + (i & 1) * 8;
                int col = h * HDc + kt * 16 + (i >> 1) * 8 + tig * 2;
                qfh[kt][i] = *(const uint32_t*)&qhg[(size_t)row * Hc + col];
                qfl[kt][i] = *(const uint32_t*)&qlg[(size_t)row * Hc + col];
            }
        }
    }

    float o[8][4];
#pragma unroll
    for (int dn = 0; dn < 8; dn++)
#pragma unroll
        for (int i = 0; i < 4; i++) o[dn][i] = 0.f;
    float m0 = -1e30f, m1 = -1e30f, l0 = 0.f, l1 = 0.f;

    const size_t kvbase = ((size_t)(b * NKVc + hkv)) * Sc;

    {
        uint32_t bb = sbase;
#pragma unroll
        for (int i = 0; i < 4; i++) {
            int chunk = tid + i * 128;
            int r = chunk >> 3, cc = chunk & 7;
            uint32_t so = (uint32_t)(r * FPITCHB + cc * 16);
            size_t go = (kvbase + r) * HDc + cc * 8;
            cp_async16(bb + so,            khg + go);
            cp_async16(bb + FARR + so,     klg + go);
            cp_async16(bb + 2 * FARR + so, vhg + go);
            cp_async16(bb + 3 * FARR + so, vlg + go);
        }
        CP_COMMIT();
    }

    for (int kb = 0; kb <= qb; kb++) {
        CP_WAIT0();
        __syncthreads();

        if (kb + 1 <= qb) {
            uint32_t bb = sbase + (uint32_t)((kb + 1) & 1) * FBUF;
#pragma unroll
            for (int i = 0; i < 4; i++) {
                int chunk = tid + i * 128;
                int r = chunk >> 3, cc = chunk & 7;
                uint32_t so = (uint32_t)(r * FPITCHB + cc * 16);
                size_t go = (kvbase + (kb + 1) * 64 + r) * HDc + cc * 8;
                cp_async16(bb + so,            khg + go);
                cp_async16(bb + FARR + so,     klg + go);
                cp_async16(bb + 2 * FARR + so, vhg + go);
                cp_async16(bb + 3 * FARR + so, vlg + go);
            }
            CP_COMMIT();
        }

        uint32_t sb = sbase + (uint32_t)(kb & 1) * FBUF;

        float s[8][4];
#pragma unroll
        for (int nt = 0; nt < 8; nt++)
#pragma unroll
            for (int i = 0; i < 4; i++) s[nt][i] = 0.f;

#pragma unroll
        for (int kt = 0; kt < 4; kt++) {
            uint32_t kfh[4][4], kfl[4][4];
#pragma unroll
            for (int kg = 0; kg < 4; kg++) {
                uint32_t addr = sb + (uint32_t)(kg * 16 * FPITCHB) + (uint32_t)(kt * 32) + boffl;
                LDSM4(kfh[kg], addr);
                LDSM4(kfl[kg], addr + FARR);
            }
#pragma unroll
            for (int kg = 0; kg < 4; kg++)
#pragma unroll
                for (int hh = 0; hh < 2; hh++)
                    mma_f16(s[kg * 2 + hh], qfh[kt], &kfh[kg][hh * 2]);
#pragma unroll
            for (int kg = 0; kg < 4; kg++)
#pragma unroll
                for (int hh = 0; hh < 2; hh++)
                    mma_f16(s[kg * 2 + hh], qfh[kt], &kfl[kg][hh * 2]);
#pragma unroll
            for (int kg = 0; kg < 4; kg++)
#pragma unroll
                for (int hh = 0; hh < 2; hh++)
                    mma_f16(s[kg * 2 + hh], qfl[kt], &kfh[kg][hh * 2]);
        }

        if (kb == qb) {
            int rl0 = w * 16 + grp;
            int rl1 = rl0 + 8;
#pragma unroll
            for (int nt = 0; nt < 8; nt++) {
                int cl = nt * 8 + tig * 2;
                if (cl     > rl0) s[nt][0] = -1e30f;
                if (cl + 1 > rl0) s[nt][1] = -1e30f;
                if (cl     > rl1) s[nt][2] = -1e30f;
                if (cl + 1 > rl1) s[nt][3] = -1e30f;
            }
        }

        {
            float mx0 = -1e30f, mx1 = -1e30f;
#pragma unroll
            for (int nt = 0; nt < 8; nt++) {
                mx0 = fmaxf(mx0, fmaxf(s[nt][0], s[nt][1]));
                mx1 = fmaxf(mx1, fmaxf(s[nt][2], s[nt][3]));
            }
            mx0 = fmaxf(mx0, __shfl_xor_sync(0xffffffffu, mx0, 1));
            mx0 = fmaxf(mx0, __shfl_xor_sync(0xffffffffu, mx0, 2));
            mx1 = fmaxf(mx1, __shfl_xor_sync(0xffffffffu, mx1, 1));
            mx1 = fmaxf(mx1, __shfl_xor_sync(0xffffffffu, mx1, 2));
            float mn0 = fmaxf(m0, mx0);
            float mn1 = fmaxf(m1, mx1);
            float a0 = __expf(m0 - mn0);
            float a1 = __expf(m1 - mn1);
            float su0 = 0.f, su1 = 0.f;
#pragma unroll
            for (int nt = 0; nt < 8; nt++) {
                s[nt][0] = __expf(s[nt][0] - mn0); su0 += s[nt][0];
                s[nt][1] = __expf(s[nt][1] - mn0); su0 += s[nt][1];
                s[nt][2] = __expf(s[nt][2] - mn1); su1 += s[nt][2];
                s[nt][3] = __expf(s[nt][3] - mn1); su1 += s[nt][3];
            }
            su0 += __shfl_xor_sync(0xffffffffu, su0, 1);
            su0 += __shfl_xor_sync(0xffffffffu, su0, 2);
            su1 += __shfl_xor_sync(0xffffffffu, su1, 1);
            su1 += __shfl_xor_sync(0xffffffffu, su1, 2);
            l0 = l0 * a0 + su0;
            l1 = l1 * a1 + su1;
            m0 = mn0;
            m1 = mn1;
#pragma unroll
            for (int dn = 0; dn < 8; dn++) {
                o[dn][0] *= a0; o[dn][1] *= a0;
                o[dn][2] *= a1; o[dn][3] *= a1;
            }
        }

        // PV with exact 2-term P: Phi*Vhi + Phi*Vlo + Plo*Vhi
#pragma unroll
        for (int kt = 0; kt < 4; kt++) {
            uint32_t ah[4], al[4];
#pragma unroll
            for (int q4 = 0; q4 < 4; q4++) {
                int nt = 2 * kt + (q4 >> 1);
                int bs = (q4 & 1) * 2;
                float p0 = s[nt][bs], p1 = s[nt][bs + 1];
                __half h0 = __float2half_rn(p0);
                __half h1v = __float2half_rn(p1);
                float lo0 = p0 - __half2float(h0);
                float lo1 = p1 - __half2float(h1v);
                __half2 hp; hp.x = h0; hp.y = h1v;
                ah[q4] = *(uint32_t*)&hp;
                al[q4] = packh2(lo0, lo1);
            }
            uint32_t vfh[4][4], vfl[4][4];
#pragma unroll
            for (int db = 0; db < 4; db++) {
                uint32_t addr = sb + 2 * FARR + (uint32_t)(kt * 16 * FPITCHB) + (uint32_t)(db * 32) + voffl;
                LDSM4T(vfh[db], addr);
                LDSM4T(vfl[db], addr + FARR);
            }
#pragma unroll
            for (int db = 0; db < 4; db++)
#pragma unroll
                for (int hh = 0; hh < 2; hh++)
                    mma_f16(o[db * 2 + hh], ah, &vfh[db][hh * 2]);
#pragma unroll
            for (int db = 0; db < 4; db++)
#pragma unroll
                for (int hh = 0; hh < 2; hh++)
                    mma_f16(o[db * 2 + hh], ah, &vfl[db][hh * 2]);
#pragma unroll
            for (int db = 0; db < 4; db++)
#pragma unroll
                for (int hh = 0; hh < 2; hh++)
                    mma_f16(o[db * 2 + hh], al, &vfh[db][hh * 2]);
        }
    }

    {
        float i0 = 1.0f / l0;
        float i1 = 1.0f / l1;
        size_t row0 = (size_t)(b * Sc + qb * 64 + w * 16 + grp);
#pragma unroll
        for (int dn = 0; dn < 8; dn++) {
            int col = h * HDc + dn * 8 + tig * 2;
            __half2 p0 = __floats2half2_rn(o[dn][0] * i0, o[dn][1] * i0);
            __half2 p1 = __floats2half2_rn(o[dn][2] * i1, o[dn][3] * i1);
            *(__half2*)&aout[row0 * Hc + col] = p0;
            *(__half2*)&aout[(row0 + 8) * Hc + col] = p1;
        }
    }
}

// ---------------------------------------------------------------------------
// Launch
// ---------------------------------------------------------------------------
extern "C" void kernel_launch(void* const* d_in, const int* in_sizes, int n_in,
                              void* d_out, int out_size) {
    const int*   input_ids = (const int*)d_in[0];
    const int*   positions = (const int*)d_in[1];
    const float* embed     = (const float*)d_in[2];
    const float* w_qkv     = (const float*)d_in[3];
    const float* w_o       = (const float*)d_in[4];
    const float* w_gate_up = (const float*)d_in[5];
    const float* w_down    = (const float*)d_in[6];
    const float* ln1_w     = (const float*)d_in[7];
    const float* ln2_w     = (const float*)d_in[8];
    const float* norm_w    = (const float*)d_in[9];
    float* out = (float*)d_out;

    float *res;
    __half *hn, *at, *ac, *wh, *wl, *qh, *ql, *kh, *kl, *vh, *vl;
    cudaGetSymbolAddress((void**)&res,  g_res);
    cudaGetSymbolAddress((void**)&hn,   g_hn);
    cudaGetSymbolAddress((void**)&at,   g_at);
    cudaGetSymbolAddress((void**)&ac,   g_ac);
    cudaGetSymbolAddress((void**)&wh,   g_wh);
    cudaGetSymbolAddress((void**)&wl,   g_wl);
    cudaGetSymbolAddress((void**)&qh,   g_qh);
    cudaGetSymbolAddress((void**)&ql,   g_ql);
    cudaGetSymbolAddress((void**)&kh,   g_kh);
    cudaGetSymbolAddress((void**)&kl,   g_kl);
    cudaGetSymbolAddress((void**)&vh,   g_vh);
    cudaGetSymbolAddress((void**)&vl,   g_vl);

    cudaFuncSetAttribute(flash_mma, cudaFuncAttributeMaxDynamicSharedMemorySize, FLASH_SMEM);
    cudaFuncSetAttribute(gemm_f16<2>, cudaFuncAttributeMaxDynamicSharedMemorySize, GEMM_SMEM);
    cudaFuncSetAttribute(gemm_f16<1>, cudaFuncAttributeMaxDynamicSharedMemorySize, GEMM_SMEM);

    prep_weights<<<2 * TILES_PER_LAYER, dim3(32, 8)>>>(
        w_qkv, w_o, w_gate_up, w_down, wh, wl);

    embed_kernel<<<Tc, 256>>>(input_ids, embed, res);

    for (int l = 0; l < Lc; l++) {
        __half* whl = wh + (size_t)l * WT_PER_L;
        __half* wll = wl + (size_t)l * WT_PER_L;

        addnorm_kernel<<<Tc, 256>>>(res, ln1_w + (size_t)l * Hc, nullptr, hn);

        // QKV projection with fused RoPE + split-fp16 scatter
        gemm_f16<2><<<dim3(Tc / 128, QKVN / 128), 256, GEMM_SMEM>>>(
            hn, whl + WT_QKV_OFF, wll + WT_QKV_OFF, nullptr, nullptr, nullptr,
            qh, ql, kh, kl, vh, vl, positions, Tc, QKVN, Hc);

        flash_mma<<<dim3(Sc / 64, NHc, Bc), 128, FLASH_SMEM>>>(
            qh, ql, kh, kl, vh, vl, at);

        gemm_f16<2><<<dim3(Tc / 128, Hc / 128), 256, GEMM_SMEM>>>(
            at, whl + WT_O_OFF, wll + WT_O_OFF, res, res, nullptr,
            nullptr, nullptr, nullptr, nullptr, nullptr, nullptr, nullptr,
            Tc, Hc, Hc);

        addnorm_kernel<<<Tc, 256>>>(res, ln2_w + (size_t)l * Hc, nullptr, hn);

        // gate_up: 1-term fp16 weights + fused SwiGLU
        gemm_f16<1><<<dim3(Tc / 128, GUN / 128), 256, GEMM_SMEM>>>(
            hn, whl + WT_GU_OFF, nullptr, nullptr, nullptr, ac,
            nullptr, nullptr, nullptr, nullptr, nullptr, nullptr, nullptr,
            Tc, GUN, Hc);

        // down-proj: 1-term fp16 weights (budget traded from exact P) + residual add
        gemm_f16<1><<<dim3(Tc / 128, Hc / 128), 256, GEMM_SMEM>>>(
            ac, whl + WT_DN_OFF, nullptr, res, res, nullptr,
            nullptr, nullptr, nullptr, nullptr, nullptr, nullptr, nullptr,
            Tc, Hc, Ic);
    }

    addnorm_kernel<<<Tc, 256>>>(res, norm_w, out, nullptr);
}